// round 9
// baseline (speedup 1.0000x reference)
#include <cuda_runtime.h>
#include <math.h>

#define B 2048
#define A1_PER (64*225)       // 14400
#define A2_PER (32*36)        // 1152
#define H_PER 512
#define KCB 100
#define BN_EPS 1e-5f

#define RECON_OFF 0
#define H_OFF     (B*H_PER)
#define LOSS_OFF  (2*B*H_PER)
#define LP_OFF    (2*B*H_PER + 1)

typedef unsigned long long u64;

// ---------------- device scratch ----------------
__device__ __align__(16) float g_a1[B*A1_PER];   // conv1 out [n][co][225] (pre-BN)
__device__ __align__(16) float g_a2[B*A2_PER];   // conv2 out [n][pos36][co32]
__device__ __align__(16) float g_hp[B*H_PER];    // conv3 out [n][co][16]
__device__ __align__(16) float2 g_w1p[3*64*10];  // conv1 dup-pairs (w,w) [ci][co][10]
__device__ __align__(16) float2 g_w2p[64*16*10]; // conv2 co-pairs [ci][cp][10]
__device__ __align__(16) float  g_w3p[32*32*12]; // conv3 [ci][co][12]
__device__ float g_sum1[64], g_ssq1[64];
__device__ float g_sum2[32], g_ssq2[32];
__device__ float g_sum3[32], g_ssq3[32];
__device__ float g_cbsq[KCB];
__device__ float g_vq;

__device__ __forceinline__ float wredsum(float v) {
#pragma unroll
    for (int o = 16; o; o >>= 1) v += __shfl_down_sync(0xffffffffu, v, o);
    return v;
}
__device__ __forceinline__ u64 pack2(float x, float y) {
    u64 r; asm("mov.b64 %0, {%1,%2};" : "=l"(r) : "f"(x), "f"(y)); return r;
}
__device__ __forceinline__ u64 dup2(float x) { return pack2(x, x); }
__device__ __forceinline__ u64 fma2(u64 a, u64 b, u64 c) {
    u64 d; asm("fma.rn.f32x2 %0, %1, %2, %3;" : "=l"(d) : "l"(a), "l"(b), "l"(c)); return d;
}
__device__ __forceinline__ float2 unpack2(u64 a) {
    float2 f; asm("mov.b64 {%0,%1}, %2;" : "=f"(f.x), "=f"(f.y) : "l"(a)); return f;
}

// ---------------- setup: init + weight repack (idempotent) ----------------
__global__ void k_setup(const float* __restrict__ cb, const float* __restrict__ w1,
                        const float* __restrict__ w2, const float* __restrict__ w3) {
    int t = blockIdx.x * blockDim.x + threadIdx.x;
    if (t < 64) { g_sum1[t] = 0.f; g_ssq1[t] = 0.f; }
    if (t < 32) { g_sum2[t] = 0.f; g_ssq2[t] = 0.f; g_sum3[t] = 0.f; g_ssq3[t] = 0.f; }
    if (t == 0) g_vq = 0.f;
    if (t < KCB) {
        float s = 0.f;
#pragma unroll
        for (int c = 0; c < 32; c++) { float v = cb[t*32+c]; s = fmaf(v, v, s); }
        g_cbsq[t] = s;
    }
    if (t < 1920) {                       // conv1 dup pairs [ci][co][10]
        int k = t % 10, r = t / 10, ci = r / 64, co = r % 64;
        float v = (k < 9) ? w1[co*27 + ci*9 + k] : 0.f;
        g_w1p[t] = make_float2(v, v);
    }
    if (t < 10240) {                      // conv2 co-pairs [ci][cp][10]
        int k = t % 10, r = t / 10, ci = r / 16, cp = r % 16;
        float a = 0.f, b = 0.f;
        if (k < 9) { a = w2[(2*cp)*576 + ci*9 + k]; b = w2[(2*cp+1)*576 + ci*9 + k]; }
        g_w2p[t] = make_float2(a, b);
    }
    if (t < 12288) {                      // conv3 [ci][co][12]
        int k = t % 12, r = t / 12, ci = r / 32, co = r % 32;
        g_w3p[t] = (k < 9) ? w3[co*288 + ci*9 + k] : 0.f;
    }
}

// ---------------- conv1 (r3 structure + 3 blocks/SM) ----------------
__global__ void __launch_bounds__(256, 3) k_conv1(const float* __restrict__ x,
                                                  const float* __restrict__ bias) {
    __shared__ __align__(16) float  sx[3*32*34];
    __shared__ __align__(16) float2 sw[1920];
    __shared__ float sb[64];
    int n = blockIdx.x, tid = threadIdx.x;

    const float4* x4 = (const float4*)(x + (size_t)n * 3072);
    for (int i = tid; i < 768; i += 256) {
        float4 v = x4[i];
        int e = i * 4, ci = e >> 10, rem = e & 1023, y = rem >> 5, xc = rem & 31;
        float* d = sx + ci*1088 + y*34 + xc;
        d[0] = v.x; d[1] = v.y; d[2] = v.z; d[3] = v.w;
    }
    {
        const float4* wsrc = (const float4*)g_w1p;
        float4* wdst = (float4*)sw;
        for (int i = tid; i < 960; i += 256) wdst[i] = wsrc[i];
    }
    if (tid < 64) sb[tid] = bias[tid];
    __syncthreads();

    for (int it = tid; it < 1800; it += 256) {
        int pos = it % 225, cg = it / 225;
        int py2 = (pos / 15) * 2, px2 = (pos % 15) * 2;
        u64 acc01[8], acc23[8];
#pragma unroll
        for (int c = 0; c < 8; c++) { acc01[c] = 0ull; acc23[c] = 0ull; }

#pragma unroll
        for (int ci = 0; ci < 3; ci++) {
            const float* spb = sx + ci*1088 + py2*34 + px2;
            u64 pr[4][3];
#pragma unroll
            for (int r = 0; r < 4; r++) {
                float2 q0 = *(const float2*)(spb + r*34);
                float2 q1 = *(const float2*)(spb + r*34 + 2);
                pr[r][0] = pack2(q0.x, q0.y);
                pr[r][1] = pack2(q0.y, q1.x);
                pr[r][2] = pack2(q1.x, q1.y);
            }
            const ulonglong2* wv = (const ulonglong2*)(sw + (ci*64 + cg*8)*10);
#pragma unroll
            for (int co = 0; co < 8; co++) {
                ulonglong2 wa = wv[co*5+0], wb = wv[co*5+1], wc = wv[co*5+2],
                           wd = wv[co*5+3], we = wv[co*5+4];
                u64 wk[9] = {wa.x, wa.y, wb.x, wb.y, wc.x, wc.y, wd.x, wd.y, we.x};
#pragma unroll
                for (int ky = 0; ky < 3; ky++)
#pragma unroll
                    for (int kx = 0; kx < 3; kx++) {
                        acc01[co] = fma2(wk[ky*3+kx], pr[ky  ][kx], acc01[co]);
                        acc23[co] = fma2(wk[ky*3+kx], pr[ky+1][kx], acc23[co]);
                    }
            }
        }
#pragma unroll
        for (int co = 0; co < 8; co++) {
            float2 a = unpack2(acc01[co]), b2v = unpack2(acc23[co]);
            int cog = cg*8 + co;
            float v = fmaxf(fmaxf(a.x, a.y), fmaxf(b2v.x, b2v.y)) + sb[cog];
            g_a1[(size_t)n*A1_PER + cog*225 + pos] = fmaxf(v, 0.f);
        }
    }
}

// ---------------- stats0 v2: one block per sample, warp = 8 channels ----------------
__global__ void __launch_bounds__(256) k_stats0() {
    int n = blockIdx.x;
    int warp = threadIdx.x >> 5, lane = threadIdx.x & 31;
    const float* base = g_a1 + (size_t)n*A1_PER + warp*8*225;
    float s[8], q[8];
#pragma unroll
    for (int c = 0; c < 8; c++) { s[c] = 0.f; q[c] = 0.f; }
#pragma unroll
    for (int c = 0; c < 8; c++) {
        const float* p = base + c*225;
        for (int i = lane; i < 225; i += 32) {
            float v = p[i]; s[c] += v; q[c] = fmaf(v, v, q[c]);
        }
    }
#pragma unroll
    for (int c = 0; c < 8; c++) {
        float a = wredsum(s[c]);
        float b = wredsum(q[c]);
        if (lane == 0) {
            atomicAdd(g_sum1 + warp*8 + c, a);
            atomicAdd(g_ssq1 + warp*8 + c, b);
        }
    }
}

// ---------------- conv2 v8 (unchanged, 825µs-proven) ----------------
#define C2P 22
__global__ void __launch_bounds__(288, 3) k_conv2(const float* __restrict__ c2b,
                                                  const float* __restrict__ bn1s,
                                                  const float* __restrict__ bn1b) {
    __shared__ __align__(16) float  sin[2*16*15*C2P];   // 10560 f, [s][ci][y:15][x pitch22]
    __shared__ __align__(16) float2 swp[16*16*10];      // [ci][cp][10] (20480B)
    __shared__ float sg1[64], sb1[64];
    __shared__ float ssum[32], sssq[32];
    int n0 = blockIdx.x * 2, tid = threadIdx.x;
    int s = tid / 144, r = tid % 144, pg = r % 36, cog = r / 36;
    int y0 = (pg / 6) * 2, x0 = (pg % 6) * 2;

    if (tid < 64) {
        float m  = g_sum1[tid] * (1.f / 460800.f);
        float vv = fmaxf(g_ssq1[tid] * (1.f / 460800.f) - m*m, 0.f);
        float gg = bn1s[tid] * rsqrtf(vv + BN_EPS);
        sg1[tid] = gg; sb1[tid] = bn1b[tid] - m * gg;
    }
    if (tid < 32) { ssum[tid] = 0.f; sssq[tid] = 0.f; }

    u64 acc[4][4];
#pragma unroll
    for (int j = 0; j < 4; j++)
#pragma unroll
        for (int p = 0; p < 4; p++) acc[j][p] = 0ull;

    for (int ch = 0; ch < 4; ch++) {
        __syncthreads();
        for (int i = tid; i < 7200; i += 288) {
            int ss = i / 3600, j = i % 3600, ci = j / 225, rem = j % 225;
            int y = rem / 15, xx = rem % 15;
            int c = ch*16 + ci;
            sin[(ss*16 + ci)*330 + y*C2P + xx] =
                fmaf(g_a1[(size_t)(n0+ss)*A1_PER + c*225 + rem], sg1[c], sb1[c]);
        }
        {
            const float4* wsrc = (const float4*)(g_w2p + (size_t)ch*2560);
            float4* wdst = (float4*)swp;
            for (int i = tid; i < 1280; i += 288) wdst[i] = wsrc[i];
        }
        __syncthreads();

        const float* sp = sin + s*16*330 + y0*C2P + x0;
#pragma unroll 2
        for (int ci = 0; ci < 16; ci++) {
            u64 pp[4][4];
#pragma unroll
            for (int rr = 0; rr < 4; rr++) {
                float2 f01 = *(const float2*)(sp + ci*330 + rr*C2P);
                float2 f23 = *(const float2*)(sp + ci*330 + rr*C2P + 2);
                pp[rr][0] = dup2(f01.x); pp[rr][1] = dup2(f01.y);
                pp[rr][2] = dup2(f23.x); pp[rr][3] = dup2(f23.y);
            }
            const ulonglong2* wv = (const ulonglong2*)(swp + (ci*16 + cog*4)*10);
#pragma unroll
            for (int j = 0; j < 4; j++) {
                ulonglong2 wa = wv[j*5+0], wb = wv[j*5+1], wc = wv[j*5+2],
                           wd = wv[j*5+3], we = wv[j*5+4];
                u64 wk[9] = {wa.x, wa.y, wb.x, wb.y, wc.x, wc.y, wd.x, wd.y, we.x};
#pragma unroll
                for (int ky = 0; ky < 3; ky++)
#pragma unroll
                    for (int kx = 0; kx < 3; kx++) {
                        u64 w = wk[ky*3+kx];
                        acc[j][0] = fma2(w, pp[ky  ][kx  ], acc[j][0]);
                        acc[j][1] = fma2(w, pp[ky  ][kx+1], acc[j][1]);
                        acc[j][2] = fma2(w, pp[ky+1][kx  ], acc[j][2]);
                        acc[j][3] = fma2(w, pp[ky+1][kx+1], acc[j][3]);
                    }
            }
        }
    }

#pragma unroll
    for (int j = 0; j < 4; j++) {
        float2 a0 = unpack2(acc[j][0]), a1v = unpack2(acc[j][1]);
        float2 a2v = unpack2(acc[j][2]), a3 = unpack2(acc[j][3]);
        int co = cog*8 + 2*j;
        float va = fmaxf(fmaxf(a0.x, a1v.x), fmaxf(a2v.x, a3.x)) + __ldg(c2b + co);
        float vb = fmaxf(fmaxf(a0.y, a1v.y), fmaxf(a2v.y, a3.y)) + __ldg(c2b + co + 1);
        va = fmaxf(va, 0.f); vb = fmaxf(vb, 0.f);
        *(float2*)(g_a2 + ((size_t)(n0+s)*36 + pg)*32 + co) = make_float2(va, vb);
        atomicAdd(&ssum[co],   va); atomicAdd(&sssq[co],   va*va);
        atomicAdd(&ssum[co+1], vb); atomicAdd(&sssq[co+1], vb*vb);
    }
    __syncthreads();
    if (tid < 32) {
        atomicAdd(g_sum2 + tid, ssum[tid]);
        atomicAdd(g_ssq2 + tid, sssq[tid]);
    }
}

// ---------------- conv3 (r5 proven, fused BN2 coef) ----------------
#define C3_SW   0
#define C3_SIN  12288
#define C3_ST   17040
#define C3_CF   17104
#define CONV3_SMEM (17168 * 4)
__global__ void __launch_bounds__(256) k_conv3(const float* __restrict__ bias,
                                               const float* __restrict__ bn2s,
                                               const float* __restrict__ bn2b) {
    extern __shared__ __align__(16) float sm3[];
    float* sw3  = sm3 + C3_SW;
    float* sin2 = sm3 + C3_SIN;
    float* ssum = sm3 + C3_ST;
    float* sssq = sm3 + C3_ST + 32;
    float* sg2  = sm3 + C3_CF;
    float* sb2c = sm3 + C3_CF + 32;
    int n0 = blockIdx.x * 4, tid = threadIdx.x;

    if (tid < 32) {
        float m  = g_sum2[tid] * (1.f / 73728.f);
        float vv = fmaxf(g_ssq2[tid] * (1.f / 73728.f) - m*m, 0.f);
        float gg = bn2s[tid] * rsqrtf(vv + BN_EPS);
        sg2[tid] = gg; sb2c[tid] = bn2b[tid] - m * gg;
        ssum[tid] = 0.f; sssq[tid] = 0.f;
    }
    __syncthreads();

    {
        const float4* wsrc = (const float4*)g_w3p;
        float4* wdst = (float4*)sw3;
        for (int i = tid; i < 3072; i += 256) wdst[i] = wsrc[i];
    }
    for (int i = tid; i < 4608; i += 256) {
        int s = i / 1152, j = i % 1152, pos = j / 32, c = j & 31;
        sin2[s*1188 + pos*33 + c] = fmaf(g_a2[(size_t)(n0+s)*A2_PER + j], sg2[c], sb2c[c]);
    }
    __syncthreads();

    int s = tid / 64, r = tid % 64, pos = r % 16, grp = r / 16;
    int py = pos / 4, px = pos % 4;
    float acc[8];
#pragma unroll
    for (int a = 0; a < 8; a++) acc[a] = 0.f;

    const float* sb2 = sin2 + s*1188;
    for (int ci = 0; ci < 32; ci++) {
        float p[9];
#pragma unroll
        for (int ky = 0; ky < 3; ky++)
#pragma unroll
            for (int kx = 0; kx < 3; kx++) p[ky*3+kx] = sb2[((py+ky)*6 + px+kx)*33 + ci];
        const float* wb = sw3 + (ci*32 + grp*8)*12;
#pragma unroll
        for (int cl = 0; cl < 8; cl++) {
            const float4* w4 = (const float4*)(wb + cl*12);
            float4 wa = w4[0], wc = w4[1];
            float wv[9] = {wa.x, wa.y, wa.z, wa.w, wc.x, wc.y, wc.z, wc.w, wb[cl*12+8]};
            float a = acc[cl];
#pragma unroll
            for (int k = 0; k < 9; k++) a = fmaf(wv[k], p[k], a);
            acc[cl] = a;
        }
    }
#pragma unroll
    for (int cl = 0; cl < 8; cl++) {
        int co = grp*8 + cl;
        float v = fmaxf(acc[cl] + bias[co], 0.f);
        g_hp[(size_t)(n0+s)*H_PER + co*16 + pos] = v;
        atomicAdd(&ssum[co], v);
        atomicAdd(&sssq[co], v*v);
    }
    __syncthreads();
    if (tid < 32) {
        atomicAdd(g_sum3 + tid, ssum[tid]);
        atomicAdd(g_ssq3 + tid, sssq[tid]);
    }
}

// ---------------- VQ + blend + FC1 + FC2 + log_softmax (r5 proven) ----------------
__global__ void __launch_bounds__(128) k_vqfc(const float* __restrict__ cb,
                                              const float* __restrict__ fc1w,
                                              const float* __restrict__ fc1b,
                                              const float* __restrict__ fc2w,
                                              const float* __restrict__ fc2b,
                                              const float* __restrict__ bn3s,
                                              const float* __restrict__ bn3b,
                                              float* __restrict__ out) {
    __shared__ float scb[KCB*32];
    __shared__ float scbsq[KCB];
    __shared__ float hs[512];
    __shared__ float bl[512];
    __shared__ float z1[64];
    __shared__ int   idxs[16];
    __shared__ float wred[4];
    __shared__ float sg3[32], sb3c[32];
    int n = blockIdx.x, tid = threadIdx.x;
    unsigned full = 0xffffffffu;

    if (tid < 32) {
        float m  = g_sum3[tid] * (1.f / 32768.f);
        float vv = fmaxf(g_ssq3[tid] * (1.f / 32768.f) - m*m, 0.f);
        float gg = bn3s[tid] * rsqrtf(vv + BN_EPS);
        sg3[tid] = gg; sb3c[tid] = bn3b[tid] - m * gg;
    }
    __syncthreads();

    for (int i = tid; i < KCB*32; i += 128) scb[i] = cb[i];
    if (tid < KCB) scbsq[tid] = g_cbsq[tid];
    for (int i = tid; i < 512; i += 128) {
        int c = i >> 4;
        float v = fmaf(g_hp[(size_t)n*H_PER + i], sg3[c], sb3c[c]);
        hs[i] = v;
        out[H_OFF + (size_t)n*512 + i] = v;
    }
    __syncthreads();

    int pos = tid >> 3, sub = tid & 7;
    float z[32];
#pragma unroll
    for (int c = 0; c < 32; c++) z[c] = hs[c*16 + pos];
    float zz = 0.f;
#pragma unroll
    for (int c = 0; c < 32; c++) zz = fmaf(z[c], z[c], zz);
    float bd = INFINITY; int bi = 0;
    for (int k = sub; k < KCB; k += 8) {
        const float* cp = scb + k*32;
        float dot = 0.f;
#pragma unroll
        for (int c = 0; c < 32; c++) dot = fmaf(cp[c], z[c], dot);
        float d = zz + scbsq[k] - 2.f*dot;
        if (d < bd) { bd = d; bi = k; }
    }
#pragma unroll
    for (int off = 4; off; off >>= 1) {
        float od = __shfl_down_sync(full, bd, off, 8);
        int   oi = __shfl_down_sync(full, bi, off, 8);
        if (od < bd || (od == bd && oi < bi)) { bd = od; bi = oi; }
    }
    if (sub == 0) idxs[pos] = bi;
    __syncthreads();

    float vqs = 0.f;
    for (int i = tid; i < 512; i += 128) {
        int c = i >> 4, p2 = i & 15;
        float q = scb[idxs[p2]*32 + c];
        float zv = hs[i];
        float df = q - zv;
        vqs = fmaf(df, df, vqs);
        out[RECON_OFF + (size_t)n*512 + i] = q;
        bl[i] = fmaf(0.5f, q, zv);
    }
    vqs = wredsum(vqs);
    if ((tid & 31) == 0) wred[tid >> 5] = vqs;
    __syncthreads();
    if (tid == 0) atomicAdd(&g_vq, wred[0] + wred[1] + wred[2] + wred[3]);

    int warp = tid >> 5, lane = tid & 31;
    for (int r = 0; r < 16; r++) {
        int o = warp*16 + r;
        const float* wp = fc1w + o*512;
        float a = 0.f;
#pragma unroll
        for (int t = 0; t < 16; t++) a = fmaf(wp[lane + 32*t], bl[lane + 32*t], a);
        a = wredsum(a);
        if (lane == 0) z1[o] = fmaxf(a + fc1b[o], 0.f);
    }
    __syncthreads();

    if (warp == 0) {
        float y = -INFINITY;
        if (lane < 10) {
            const float* wp = fc2w + lane*64;
            float a = 0.f;
#pragma unroll
            for (int j = 0; j < 64; j++) a = fmaf(wp[j], z1[j], a);
            y = a + fc2b[lane];
        }
        float m = y;
#pragma unroll
        for (int off = 16; off; off >>= 1) m = fmaxf(m, __shfl_xor_sync(full, m, off));
        float e = (lane < 10) ? expf(y - m) : 0.f;
        float ssum = e;
#pragma unroll
        for (int off = 16; off; off >>= 1) ssum += __shfl_xor_sync(full, ssum, off);
        if (lane < 10) out[LP_OFF + (size_t)n*10 + lane] = y - m - logf(ssum);
    }
}

__global__ void k_final(float* __restrict__ out) {
    out[LOSS_OFF] = 1.25f * g_vq / (float)(B * 16 * 32);
}

// ---------------- launch ----------------
extern "C" void kernel_launch(void* const* d_in, const int* in_sizes, int n_in,
                              void* d_out, int out_size) {
    const float* x      = (const float*)d_in[0];
    const float* c1w    = (const float*)d_in[1];
    const float* c1b    = (const float*)d_in[2];
    const float* bn1s   = (const float*)d_in[3];
    const float* bn1b   = (const float*)d_in[4];
    const float* c2w    = (const float*)d_in[5];
    const float* c2b    = (const float*)d_in[6];
    const float* bn2s   = (const float*)d_in[7];
    const float* bn2b   = (const float*)d_in[8];
    const float* c3w    = (const float*)d_in[9];
    const float* c3b    = (const float*)d_in[10];
    const float* bn3s   = (const float*)d_in[11];
    const float* bn3b   = (const float*)d_in[12];
    const float* cb     = (const float*)d_in[13];
    const float* fc1w   = (const float*)d_in[14];
    const float* fc1b   = (const float*)d_in[15];
    const float* fc2w   = (const float*)d_in[16];
    const float* fc2b   = (const float*)d_in[17];
    float* out = (float*)d_out;

    cudaFuncSetAttribute(k_conv3, cudaFuncAttributeMaxDynamicSharedMemorySize, CONV3_SMEM);

    // k_setup is idempotent; launched 3x so k_conv1 lands on the ncu
    // capture slot (empirically launch index 3).
    k_setup<<<48, 256>>>(cb, c1w, c2w, c3w);                       // 0
    k_setup<<<48, 256>>>(cb, c1w, c2w, c3w);                       // 1
    k_setup<<<48, 256>>>(cb, c1w, c2w, c3w);                       // 2
    k_conv1<<<B, 256>>>(x, c1b);                                   // 3  <- ncu capture
    k_stats0<<<B, 256>>>();                                        // 4
    k_conv2<<<B/2, 288>>>(c2b, bn1s, bn1b);                        // 5
    k_conv3<<<B/4, 256, CONV3_SMEM>>>(c3b, bn2s, bn2b);            // 6
    k_vqfc<<<B, 128>>>(cb, fc1w, fc1b, fc2w, fc2b, bn3s, bn3b, out); // 7
    k_final<<<1, 1>>>(out);                                        // 8
}

// round 10
// speedup vs baseline: 1.0506x; 1.0506x over previous
#include <cuda_runtime.h>
#include <math.h>

#define B 2048
#define A1_PER (64*225)       // 14400
#define A2_PER (32*36)        // 1152
#define H_PER 512
#define KCB 100
#define BN_EPS 1e-5f

#define RECON_OFF 0
#define H_OFF     (B*H_PER)
#define LOSS_OFF  (2*B*H_PER)
#define LP_OFF    (2*B*H_PER + 1)

typedef unsigned long long u64;

// ---------------- device scratch ----------------
__device__ __align__(16) float g_a1[B*A1_PER];   // conv1 out [n][co][225] (pre-BN)
__device__ __align__(16) float g_a2[B*A2_PER];   // conv2 out [n][pos36][co32]
__device__ __align__(16) float g_hp[B*H_PER];    // conv3 out [n][co][16]
__device__ __align__(16) float2 g_w1p[3*64*10];  // conv1 dup-pairs (w,w) [ci][co][10]
__device__ __align__(16) float2 g_w2p[64*16*10]; // conv2 co-pairs [ci][cp][10]
__device__ __align__(16) float  g_w3p[32*32*12]; // conv3 [ci][co][12]
__device__ float g_sum1[64], g_ssq1[64];
__device__ float g_sum2[32], g_ssq2[32];
__device__ float g_sum3[32], g_ssq3[32];
__device__ float g_cbsq[KCB];
__device__ float g_vq;

__device__ __forceinline__ float wredsum(float v) {
#pragma unroll
    for (int o = 16; o; o >>= 1) v += __shfl_down_sync(0xffffffffu, v, o);
    return v;
}
__device__ __forceinline__ u64 pack2(float x, float y) {
    u64 r; asm("mov.b64 %0, {%1,%2};" : "=l"(r) : "f"(x), "f"(y)); return r;
}
__device__ __forceinline__ u64 dup2(float x) { return pack2(x, x); }
__device__ __forceinline__ u64 fma2(u64 a, u64 b, u64 c) {
    u64 d; asm("fma.rn.f32x2 %0, %1, %2, %3;" : "=l"(d) : "l"(a), "l"(b), "l"(c)); return d;
}
__device__ __forceinline__ float2 unpack2(u64 a) {
    float2 f; asm("mov.b64 {%0,%1}, %2;" : "=f"(f.x), "=f"(f.y) : "l"(a)); return f;
}

// ---------------- setup: init + weight repack ----------------
__global__ void k_setup(const float* __restrict__ cb, const float* __restrict__ w1,
                        const float* __restrict__ w2, const float* __restrict__ w3) {
    int t = blockIdx.x * blockDim.x + threadIdx.x;
    if (t < 64) { g_sum1[t] = 0.f; g_ssq1[t] = 0.f; }
    if (t < 32) { g_sum2[t] = 0.f; g_ssq2[t] = 0.f; g_sum3[t] = 0.f; g_ssq3[t] = 0.f; }
    if (t == 0) g_vq = 0.f;
    if (t < KCB) {
        float s = 0.f;
#pragma unroll
        for (int c = 0; c < 32; c++) { float v = cb[t*32+c]; s = fmaf(v, v, s); }
        g_cbsq[t] = s;
    }
    if (t < 1920) {                       // conv1 dup pairs [ci][co][10]
        int k = t % 10, r = t / 10, ci = r / 64, co = r % 64;
        float v = (k < 9) ? w1[co*27 + ci*9 + k] : 0.f;
        g_w1p[t] = make_float2(v, v);
    }
    if (t < 10240) {                      // conv2 co-pairs [ci][cp][10]
        int k = t % 10, r = t / 10, ci = r / 16, cp = r % 16;
        float a = 0.f, b = 0.f;
        if (k < 9) { a = w2[(2*cp)*576 + ci*9 + k]; b = w2[(2*cp+1)*576 + ci*9 + k]; }
        g_w2p[t] = make_float2(a, b);
    }
    if (t < 12288) {                      // conv3 [ci][co][12]
        int k = t % 12, r = t / 12, ci = r / 32, co = r % 32;
        g_w3p[t] = (k < 9) ? w3[co*288 + ci*9 + k] : 0.f;
    }
}

// ---------------- conv1 (proven, 173us) ----------------
__global__ void __launch_bounds__(256, 3) k_conv1(const float* __restrict__ x,
                                                  const float* __restrict__ bias) {
    __shared__ __align__(16) float  sx[3*32*34];
    __shared__ __align__(16) float2 sw[1920];
    __shared__ float sb[64];
    int n = blockIdx.x, tid = threadIdx.x;

    const float4* x4 = (const float4*)(x + (size_t)n * 3072);
    for (int i = tid; i < 768; i += 256) {
        float4 v = x4[i];
        int e = i * 4, ci = e >> 10, rem = e & 1023, y = rem >> 5, xc = rem & 31;
        float* d = sx + ci*1088 + y*34 + xc;
        d[0] = v.x; d[1] = v.y; d[2] = v.z; d[3] = v.w;
    }
    {
        const float4* wsrc = (const float4*)g_w1p;
        float4* wdst = (float4*)sw;
        for (int i = tid; i < 960; i += 256) wdst[i] = wsrc[i];
    }
    if (tid < 64) sb[tid] = bias[tid];
    __syncthreads();

    for (int it = tid; it < 1800; it += 256) {
        int pos = it % 225, cg = it / 225;
        int py2 = (pos / 15) * 2, px2 = (pos % 15) * 2;
        u64 acc01[8], acc23[8];
#pragma unroll
        for (int c = 0; c < 8; c++) { acc01[c] = 0ull; acc23[c] = 0ull; }

#pragma unroll
        for (int ci = 0; ci < 3; ci++) {
            const float* spb = sx + ci*1088 + py2*34 + px2;
            u64 pr[4][3];
#pragma unroll
            for (int r = 0; r < 4; r++) {
                float2 q0 = *(const float2*)(spb + r*34);
                float2 q1 = *(const float2*)(spb + r*34 + 2);
                pr[r][0] = pack2(q0.x, q0.y);
                pr[r][1] = pack2(q0.y, q1.x);
                pr[r][2] = pack2(q1.x, q1.y);
            }
            const ulonglong2* wv = (const ulonglong2*)(sw + (ci*64 + cg*8)*10);
#pragma unroll
            for (int co = 0; co < 8; co++) {
                ulonglong2 wa = wv[co*5+0], wb = wv[co*5+1], wc = wv[co*5+2],
                           wd = wv[co*5+3], we = wv[co*5+4];
                u64 wk[9] = {wa.x, wa.y, wb.x, wb.y, wc.x, wc.y, wd.x, wd.y, we.x};
#pragma unroll
                for (int ky = 0; ky < 3; ky++)
#pragma unroll
                    for (int kx = 0; kx < 3; kx++) {
                        acc01[co] = fma2(wk[ky*3+kx], pr[ky  ][kx], acc01[co]);
                        acc23[co] = fma2(wk[ky*3+kx], pr[ky+1][kx], acc23[co]);
                    }
            }
        }
#pragma unroll
        for (int co = 0; co < 8; co++) {
            float2 a = unpack2(acc01[co]), b2v = unpack2(acc23[co]);
            int cog = cg*8 + co;
            float v = fmaxf(fmaxf(a.x, a.y), fmaxf(b2v.x, b2v.y)) + sb[cog];
            g_a1[(size_t)n*A1_PER + cog*225 + pos] = fmaxf(v, 0.f);
        }
    }
}

// ---------------- stats0: one block per sample, warp = 8 channels ----------------
__global__ void __launch_bounds__(256) k_stats0() {
    int n = blockIdx.x;
    int warp = threadIdx.x >> 5, lane = threadIdx.x & 31;
    const float* base = g_a1 + (size_t)n*A1_PER + warp*8*225;
    float s[8], q[8];
#pragma unroll
    for (int c = 0; c < 8; c++) { s[c] = 0.f; q[c] = 0.f; }
#pragma unroll
    for (int c = 0; c < 8; c++) {
        const float* p = base + c*225;
        for (int i = lane; i < 225; i += 32) {
            float v = p[i]; s[c] += v; q[c] = fmaf(v, v, q[c]);
        }
    }
#pragma unroll
    for (int c = 0; c < 8; c++) {
        float a = wredsum(s[c]);
        float b = wredsum(q[c]);
        if (lane == 0) {
            atomicAdd(g_sum1 + warp*8 + c, a);
            atomicAdd(g_ssq1 + warp*8 + c, b);
        }
    }
}

// ---------------- conv2 v8 (unchanged, proven 335us) ----------------
#define C2P 22
__global__ void __launch_bounds__(288, 3) k_conv2(const float* __restrict__ c2b,
                                                  const float* __restrict__ bn1s,
                                                  const float* __restrict__ bn1b) {
    __shared__ __align__(16) float  sin[2*16*15*C2P];
    __shared__ __align__(16) float2 swp[16*16*10];
    __shared__ float sg1[64], sb1[64];
    __shared__ float ssum[32], sssq[32];
    int n0 = blockIdx.x * 2, tid = threadIdx.x;
    int s = tid / 144, r = tid % 144, pg = r % 36, cog = r / 36;
    int y0 = (pg / 6) * 2, x0 = (pg % 6) * 2;

    if (tid < 64) {
        float m  = g_sum1[tid] * (1.f / 460800.f);
        float vv = fmaxf(g_ssq1[tid] * (1.f / 460800.f) - m*m, 0.f);
        float gg = bn1s[tid] * rsqrtf(vv + BN_EPS);
        sg1[tid] = gg; sb1[tid] = bn1b[tid] - m * gg;
    }
    if (tid < 32) { ssum[tid] = 0.f; sssq[tid] = 0.f; }

    u64 acc[4][4];
#pragma unroll
    for (int j = 0; j < 4; j++)
#pragma unroll
        for (int p = 0; p < 4; p++) acc[j][p] = 0ull;

    for (int ch = 0; ch < 4; ch++) {
        __syncthreads();
        for (int i = tid; i < 7200; i += 288) {
            int ss = i / 3600, j = i % 3600, ci = j / 225, rem = j % 225;
            int y = rem / 15, xx = rem % 15;
            int c = ch*16 + ci;
            sin[(ss*16 + ci)*330 + y*C2P + xx] =
                fmaf(g_a1[(size_t)(n0+ss)*A1_PER + c*225 + rem], sg1[c], sb1[c]);
        }
        {
            const float4* wsrc = (const float4*)(g_w2p + (size_t)ch*2560);
            float4* wdst = (float4*)swp;
            for (int i = tid; i < 1280; i += 288) wdst[i] = wsrc[i];
        }
        __syncthreads();

        const float* sp = sin + s*16*330 + y0*C2P + x0;
#pragma unroll 2
        for (int ci = 0; ci < 16; ci++) {
            u64 pp[4][4];
#pragma unroll
            for (int rr = 0; rr < 4; rr++) {
                float2 f01 = *(const float2*)(sp + ci*330 + rr*C2P);
                float2 f23 = *(const float2*)(sp + ci*330 + rr*C2P + 2);
                pp[rr][0] = dup2(f01.x); pp[rr][1] = dup2(f01.y);
                pp[rr][2] = dup2(f23.x); pp[rr][3] = dup2(f23.y);
            }
            const ulonglong2* wv = (const ulonglong2*)(swp + (ci*16 + cog*4)*10);
#pragma unroll
            for (int j = 0; j < 4; j++) {
                ulonglong2 wa = wv[j*5+0], wb = wv[j*5+1], wc = wv[j*5+2],
                           wd = wv[j*5+3], we = wv[j*5+4];
                u64 wk[9] = {wa.x, wa.y, wb.x, wb.y, wc.x, wc.y, wd.x, wd.y, we.x};
#pragma unroll
                for (int ky = 0; ky < 3; ky++)
#pragma unroll
                    for (int kx = 0; kx < 3; kx++) {
                        u64 w = wk[ky*3+kx];
                        acc[j][0] = fma2(w, pp[ky  ][kx  ], acc[j][0]);
                        acc[j][1] = fma2(w, pp[ky  ][kx+1], acc[j][1]);
                        acc[j][2] = fma2(w, pp[ky+1][kx  ], acc[j][2]);
                        acc[j][3] = fma2(w, pp[ky+1][kx+1], acc[j][3]);
                    }
            }
        }
    }

#pragma unroll
    for (int j = 0; j < 4; j++) {
        float2 a0 = unpack2(acc[j][0]), a1v = unpack2(acc[j][1]);
        float2 a2v = unpack2(acc[j][2]), a3 = unpack2(acc[j][3]);
        int co = cog*8 + 2*j;
        float va = fmaxf(fmaxf(a0.x, a1v.x), fmaxf(a2v.x, a3.x)) + __ldg(c2b + co);
        float vb = fmaxf(fmaxf(a0.y, a1v.y), fmaxf(a2v.y, a3.y)) + __ldg(c2b + co + 1);
        va = fmaxf(va, 0.f); vb = fmaxf(vb, 0.f);
        *(float2*)(g_a2 + ((size_t)(n0+s)*36 + pg)*32 + co) = make_float2(va, vb);
        atomicAdd(&ssum[co],   va); atomicAdd(&sssq[co],   va*va);
        atomicAdd(&ssum[co+1], vb); atomicAdd(&sssq[co+1], vb*vb);
    }
    __syncthreads();
    if (tid < 32) {
        atomicAdd(g_sum2 + tid, ssum[tid]);
        atomicAdd(g_ssq2 + tid, sssq[tid]);
    }
}

// ---------------- conv3 (proven, fused BN2 coef) ----------------
#define C3_SW   0
#define C3_SIN  12288
#define C3_ST   17040
#define C3_CF   17104
#define CONV3_SMEM (17168 * 4)
__global__ void __launch_bounds__(256) k_conv3(const float* __restrict__ bias,
                                               const float* __restrict__ bn2s,
                                               const float* __restrict__ bn2b) {
    extern __shared__ __align__(16) float sm3[];
    float* sw3  = sm3 + C3_SW;
    float* sin2 = sm3 + C3_SIN;
    float* ssum = sm3 + C3_ST;
    float* sssq = sm3 + C3_ST + 32;
    float* sg2  = sm3 + C3_CF;
    float* sb2c = sm3 + C3_CF + 32;
    int n0 = blockIdx.x * 4, tid = threadIdx.x;

    if (tid < 32) {
        float m  = g_sum2[tid] * (1.f / 73728.f);
        float vv = fmaxf(g_ssq2[tid] * (1.f / 73728.f) - m*m, 0.f);
        float gg = bn2s[tid] * rsqrtf(vv + BN_EPS);
        sg2[tid] = gg; sb2c[tid] = bn2b[tid] - m * gg;
        ssum[tid] = 0.f; sssq[tid] = 0.f;
    }
    __syncthreads();

    {
        const float4* wsrc = (const float4*)g_w3p;
        float4* wdst = (float4*)sw3;
        for (int i = tid; i < 3072; i += 256) wdst[i] = wsrc[i];
    }
    for (int i = tid; i < 4608; i += 256) {
        int s = i / 1152, j = i % 1152, pos = j / 32, c = j & 31;
        sin2[s*1188 + pos*33 + c] = fmaf(g_a2[(size_t)(n0+s)*A2_PER + j], sg2[c], sb2c[c]);
    }
    __syncthreads();

    int s = tid / 64, r = tid % 64, pos = r % 16, grp = r / 16;
    int py = pos / 4, px = pos % 4;
    float acc[8];
#pragma unroll
    for (int a = 0; a < 8; a++) acc[a] = 0.f;

    const float* sb2 = sin2 + s*1188;
    for (int ci = 0; ci < 32; ci++) {
        float p[9];
#pragma unroll
        for (int ky = 0; ky < 3; ky++)
#pragma unroll
            for (int kx = 0; kx < 3; kx++) p[ky*3+kx] = sb2[((py+ky)*6 + px+kx)*33 + ci];
        const float* wb = sw3 + (ci*32 + grp*8)*12;
#pragma unroll
        for (int cl = 0; cl < 8; cl++) {
            const float4* w4 = (const float4*)(wb + cl*12);
            float4 wa = w4[0], wc = w4[1];
            float wv[9] = {wa.x, wa.y, wa.z, wa.w, wc.x, wc.y, wc.z, wc.w, wb[cl*12+8]};
            float a = acc[cl];
#pragma unroll
            for (int k = 0; k < 9; k++) a = fmaf(wv[k], p[k], a);
            acc[cl] = a;
        }
    }
#pragma unroll
    for (int cl = 0; cl < 8; cl++) {
        int co = grp*8 + cl;
        float v = fmaxf(acc[cl] + bias[co], 0.f);
        g_hp[(size_t)(n0+s)*H_PER + co*16 + pos] = v;
        atomicAdd(&ssum[co], v);
        atomicAdd(&sssq[co], v*v);
    }
    __syncthreads();
    if (tid < 32) {
        atomicAdd(g_sum3 + tid, ssum[tid]);
        atomicAdd(g_ssq3 + tid, sssq[tid]);
    }
}

// ---------------- VQ + blend + FC1 + FC2 + log_softmax (v2) ----------------
__global__ void __launch_bounds__(128) k_vqfc(const float* __restrict__ cb,
                                              const float* __restrict__ fc1w,
                                              const float* __restrict__ fc1b,
                                              const float* __restrict__ fc2w,
                                              const float* __restrict__ fc2b,
                                              const float* __restrict__ bn3s,
                                              const float* __restrict__ bn3b,
                                              float* __restrict__ out) {
    __shared__ float scb[KCB*32];        // row-major (for recon gather)
    __shared__ float scbT[32*104];       // transposed, pad 104 -> conflict-free dot
    __shared__ float scbsq[KCB];
    __shared__ float hs[512];
    __shared__ float bl[512];
    __shared__ float z1[64];
    __shared__ float z1h[128];
    __shared__ int   idxs[16];
    __shared__ float wred[4];
    __shared__ float sg3[32], sb3c[32];
    int n = blockIdx.x, tid = threadIdx.x;
    unsigned full = 0xffffffffu;

    if (tid < 32) {
        float m  = g_sum3[tid] * (1.f / 32768.f);
        float vv = fmaxf(g_ssq3[tid] * (1.f / 32768.f) - m*m, 0.f);
        float gg = bn3s[tid] * rsqrtf(vv + BN_EPS);
        sg3[tid] = gg; sb3c[tid] = bn3b[tid] - m * gg;
    }
    __syncthreads();

    for (int i = tid; i < KCB*32; i += 128) {
        float v = cb[i];
        scb[i] = v;
        scbT[(i & 31)*104 + (i >> 5)] = v;   // [c][k]
    }
    if (tid < KCB) scbsq[tid] = g_cbsq[tid];
    for (int i = tid; i < 512; i += 128) {
        int c = i >> 4;
        float v = fmaf(g_hp[(size_t)n*H_PER + i], sg3[c], sb3c[c]);
        hs[i] = v;
        out[H_OFF + (size_t)n*512 + i] = v;
    }
    __syncthreads();

    // VQ argmin: 16 positions x 8 code-subsets; conflict-free scbT reads
    int pos = tid >> 3, sub = tid & 7;
    float z[32];
#pragma unroll
    for (int c = 0; c < 32; c++) z[c] = hs[c*16 + pos];
    float zz = 0.f;
#pragma unroll
    for (int c = 0; c < 32; c++) zz = fmaf(z[c], z[c], zz);
    float bd = INFINITY; int bi = 0;
    for (int k = sub; k < KCB; k += 8) {
        float dot = 0.f;
#pragma unroll
        for (int c = 0; c < 32; c++) dot = fmaf(scbT[c*104 + k], z[c], dot);
        float d = zz + scbsq[k] - 2.f*dot;
        if (d < bd) { bd = d; bi = k; }
    }
#pragma unroll
    for (int off = 4; off; off >>= 1) {
        float od = __shfl_down_sync(full, bd, off, 8);
        int   oi = __shfl_down_sync(full, bi, off, 8);
        if (od < bd || (od == bd && oi < bi)) { bd = od; bi = oi; }
    }
    if (sub == 0) idxs[pos] = bi;
    __syncthreads();

    float vqs = 0.f;
    for (int i = tid; i < 512; i += 128) {
        int c = i >> 4, p2 = i & 15;
        float q = scb[idxs[p2]*32 + c];
        float zv = hs[i];
        float df = q - zv;
        vqs = fmaf(df, df, vqs);
        out[RECON_OFF + (size_t)n*512 + i] = q;
        bl[i] = fmaf(0.5f, q, zv);
    }
    vqs = wredsum(vqs);
    if ((tid & 31) == 0) wred[tid >> 5] = vqs;
    __syncthreads();
    if (tid == 0) atomicAdd(&g_vq, wred[0] + wred[1] + wred[2] + wred[3]);

    // FC1 v2: thread = (output o, k-half h); float4 LDG x float4 smem broadcast
    {
        int o = tid & 63, hh = tid >> 6;
        const float4* wp4 = (const float4*)(fc1w + o*512 + hh*256);
        const float4* bl4 = (const float4*)(bl + hh*256);
        float a = 0.f;
#pragma unroll 8
        for (int t = 0; t < 64; t++) {
            float4 w = wp4[t], b = bl4[t];
            a = fmaf(w.x, b.x, a); a = fmaf(w.y, b.y, a);
            a = fmaf(w.z, b.z, a); a = fmaf(w.w, b.w, a);
        }
        z1h[tid] = a;
    }
    __syncthreads();
    if (tid < 64) z1[tid] = fmaxf(z1h[tid] + z1h[64 + tid] + fc1b[tid], 0.f);
    __syncthreads();

    // FC2 + log_softmax (warp 0)
    if (tid < 32) {
        int lane = tid;
        float y = -INFINITY;
        if (lane < 10) {
            const float* wp = fc2w + lane*64;
            float a = 0.f;
#pragma unroll
            for (int j = 0; j < 64; j++) a = fmaf(wp[j], z1[j], a);
            y = a + fc2b[lane];
        }
        float m = y;
#pragma unroll
        for (int off = 16; off; off >>= 1) m = fmaxf(m, __shfl_xor_sync(full, m, off));
        float e = (lane < 10) ? expf(y - m) : 0.f;
        float ssum = e;
#pragma unroll
        for (int off = 16; off; off >>= 1) ssum += __shfl_xor_sync(full, ssum, off);
        if (lane < 10) out[LP_OFF + (size_t)n*10 + lane] = y - m - logf(ssum);
    }
}

__global__ void k_final(float* __restrict__ out) {
    out[LOSS_OFF] = 1.25f * g_vq / (float)(B * 16 * 32);
}

// ---------------- launch ----------------
extern "C" void kernel_launch(void* const* d_in, const int* in_sizes, int n_in,
                              void* d_out, int out_size) {
    const float* x      = (const float*)d_in[0];
    const float* c1w    = (const float*)d_in[1];
    const float* c1b    = (const float*)d_in[2];
    const float* bn1s   = (const float*)d_in[3];
    const float* bn1b   = (const float*)d_in[4];
    const float* c2w    = (const float*)d_in[5];
    const float* c2b    = (const float*)d_in[6];
    const float* bn2s   = (const float*)d_in[7];
    const float* bn2b   = (const float*)d_in[8];
    const float* c3w    = (const float*)d_in[9];
    const float* c3b    = (const float*)d_in[10];
    const float* bn3s   = (const float*)d_in[11];
    const float* bn3b   = (const float*)d_in[12];
    const float* cb     = (const float*)d_in[13];
    const float* fc1w   = (const float*)d_in[14];
    const float* fc1b   = (const float*)d_in[15];
    const float* fc2w   = (const float*)d_in[16];
    const float* fc2b   = (const float*)d_in[17];
    float* out = (float*)d_out;

    cudaFuncSetAttribute(k_conv3, cudaFuncAttributeMaxDynamicSharedMemorySize, CONV3_SMEM);

    k_setup<<<48, 256>>>(cb, c1w, c2w, c3w);                       // 0
    k_conv1<<<B, 256>>>(x, c1b);                                   // 1
    k_stats0<<<B, 256>>>();                                        // 2
    k_conv2<<<B/2, 288>>>(c2b, bn1s, bn1b);                        // 3  <- ncu capture (sanity: ~335us)
    k_conv3<<<B/4, 256, CONV3_SMEM>>>(c3b, bn2s, bn2b);            // 4
    k_vqfc<<<B, 128>>>(cb, fc1w, fc1b, fc2w, fc2b, bn3s, bn3b, out); // 5
    k_final<<<1, 1>>>(out);                                        // 6
}

// round 11
// speedup vs baseline: 1.1233x; 1.0692x over previous
#include <cuda_runtime.h>
#include <math.h>

#define B 2048
#define A1_PER (64*225)       // 14400
#define A2_PER (32*36)        // 1152
#define H_PER 512
#define KCB 100
#define BN_EPS 1e-5f

#define RECON_OFF 0
#define H_OFF     (B*H_PER)
#define LOSS_OFF  (2*B*H_PER)
#define LP_OFF    (2*B*H_PER + 1)

typedef unsigned long long u64;

// ---------------- device scratch ----------------
__device__ __align__(16) float g_a1[B*A1_PER];   // conv1 out [n][co][225] (pre-BN)
__device__ __align__(16) float g_a2[B*A2_PER];   // conv2 out [n][pos36][co32]
__device__ __align__(16) float g_hp[B*H_PER];    // conv3 out [n][co][16]
__device__ __align__(16) float2 g_w1p[3*64*10];  // conv1 co-pairs [ci][cp32][10] (960 used)
__device__ __align__(16) float2 g_w2p[64*16*10]; // conv2 co-pairs [ci][cp][10]
__device__ __align__(16) float  g_w3p[32*32*12]; // conv3 [ci][co][12]
__device__ float g_sum1[64], g_ssq1[64];
__device__ float g_sum2[32], g_ssq2[32];
__device__ float g_sum3[32], g_ssq3[32];
__device__ float g_cbsq[KCB];
__device__ float g_vq;

__device__ __forceinline__ float wredsum(float v) {
#pragma unroll
    for (int o = 16; o; o >>= 1) v += __shfl_down_sync(0xffffffffu, v, o);
    return v;
}
__device__ __forceinline__ u64 pack2(float x, float y) {
    u64 r; asm("mov.b64 %0, {%1,%2};" : "=l"(r) : "f"(x), "f"(y)); return r;
}
__device__ __forceinline__ u64 dup2(float x) { return pack2(x, x); }
__device__ __forceinline__ u64 fma2(u64 a, u64 b, u64 c) {
    u64 d; asm("fma.rn.f32x2 %0, %1, %2, %3;" : "=l"(d) : "l"(a), "l"(b), "l"(c)); return d;
}
__device__ __forceinline__ float2 unpack2(u64 a) {
    float2 f; asm("mov.b64 {%0,%1}, %2;" : "=f"(f.x), "=f"(f.y) : "l"(a)); return f;
}

// ---------------- setup: init + weight repack ----------------
__global__ void k_setup(const float* __restrict__ cb, const float* __restrict__ w1,
                        const float* __restrict__ w2, const float* __restrict__ w3) {
    int t = blockIdx.x * blockDim.x + threadIdx.x;
    if (t < 64) { g_sum1[t] = 0.f; g_ssq1[t] = 0.f; }
    if (t < 32) { g_sum2[t] = 0.f; g_ssq2[t] = 0.f; g_sum3[t] = 0.f; g_ssq3[t] = 0.f; }
    if (t == 0) g_vq = 0.f;
    if (t < KCB) {
        float s = 0.f;
#pragma unroll
        for (int c = 0; c < 32; c++) { float v = cb[t*32+c]; s = fmaf(v, v, s); }
        g_cbsq[t] = s;
    }
    if (t < 960) {                        // conv1 co-pairs [ci][cp32][10]
        int k = t % 10, r = t / 10, ci = r / 32, cp = r % 32;
        float a = 0.f, b = 0.f;
        if (k < 9) { a = w1[(2*cp)*27 + ci*9 + k]; b = w1[(2*cp+1)*27 + ci*9 + k]; }
        g_w1p[t] = make_float2(a, b);
    }
    if (t < 10240) {                      // conv2 co-pairs [ci][cp][10]
        int k = t % 10, r = t / 10, ci = r / 16, cp = r % 16;
        float a = 0.f, b = 0.f;
        if (k < 9) { a = w2[(2*cp)*576 + ci*9 + k]; b = w2[(2*cp+1)*576 + ci*9 + k]; }
        g_w2p[t] = make_float2(a, b);
    }
    if (t < 12288) {                      // conv3 [ci][co][12]
        int k = t % 12, r = t / 12, ci = r / 32, co = r % 32;
        g_w3p[t] = (k < 9) ? w3[co*288 + ci*9 + k] : 0.f;
    }
}

// ---------------- conv1 v2: co-paired weights (20 LDS.128/ci), dup-packed inputs ----------------
__global__ void __launch_bounds__(256, 3) k_conv1(const float* __restrict__ x,
                                                  const float* __restrict__ bias) {
    __shared__ __align__(16) float  sx[3*32*34];      // 13056 f
    __shared__ __align__(16) float2 swp1[3*32*10];    // 960 f2, co-pairs
    __shared__ float sb[64];
    int n = blockIdx.x, tid = threadIdx.x;

    const float4* x4 = (const float4*)(x + (size_t)n * 3072);
    for (int i = tid; i < 768; i += 256) {
        float4 v = x4[i];
        int e = i * 4, ci = e >> 10, rem = e & 1023, y = rem >> 5, xc = rem & 31;
        float* d = sx + ci*1088 + y*34 + xc;
        d[0] = v.x; d[1] = v.y; d[2] = v.z; d[3] = v.w;
    }
    {
        const float4* wsrc = (const float4*)g_w1p;
        float4* wdst = (float4*)swp1;
        for (int i = tid; i < 480; i += 256) wdst[i] = wsrc[i];
    }
    if (tid < 64) sb[tid] = bias[tid];
    __syncthreads();

    for (int it = tid; it < 1800; it += 256) {         // 225 pos x 8 cg (4 pairs each)
        int pos = it % 225, cg = it / 225;
        int py2 = (pos / 15) * 2, px2 = (pos % 15) * 2;
        u64 acc[4][4];                                 // [pair j][pos in window]
#pragma unroll
        for (int j = 0; j < 4; j++)
#pragma unroll
            for (int p = 0; p < 4; p++) acc[j][p] = 0ull;

#pragma unroll
        for (int ci = 0; ci < 3; ci++) {
            const float* sp = sx + ci*1088 + py2*34 + px2;
            u64 pp[4][4];
#pragma unroll
            for (int rr = 0; rr < 4; rr++) {
                float2 f01 = *(const float2*)(sp + rr*34);
                float2 f23 = *(const float2*)(sp + rr*34 + 2);
                pp[rr][0] = dup2(f01.x); pp[rr][1] = dup2(f01.y);
                pp[rr][2] = dup2(f23.x); pp[rr][3] = dup2(f23.y);
            }
            const ulonglong2* wv = (const ulonglong2*)(swp1 + (ci*32 + cg*4)*10);
#pragma unroll
            for (int j = 0; j < 4; j++) {
                ulonglong2 wa = wv[j*5+0], wb = wv[j*5+1], wc = wv[j*5+2],
                           wd = wv[j*5+3], we = wv[j*5+4];
                u64 wk[9] = {wa.x, wa.y, wb.x, wb.y, wc.x, wc.y, wd.x, wd.y, we.x};
#pragma unroll
                for (int ky = 0; ky < 3; ky++)
#pragma unroll
                    for (int kx = 0; kx < 3; kx++) {
                        u64 w = wk[ky*3+kx];
                        acc[j][0] = fma2(w, pp[ky  ][kx  ], acc[j][0]);
                        acc[j][1] = fma2(w, pp[ky  ][kx+1], acc[j][1]);
                        acc[j][2] = fma2(w, pp[ky+1][kx  ], acc[j][2]);
                        acc[j][3] = fma2(w, pp[ky+1][kx+1], acc[j][3]);
                    }
            }
        }
#pragma unroll
        for (int j = 0; j < 4; j++) {
            float2 a0 = unpack2(acc[j][0]), a1v = unpack2(acc[j][1]);
            float2 a2v = unpack2(acc[j][2]), a3 = unpack2(acc[j][3]);
            int co = cg*8 + 2*j;
            float va = fmaxf(fmaxf(a0.x, a1v.x), fmaxf(a2v.x, a3.x)) + sb[co];
            float vb = fmaxf(fmaxf(a0.y, a1v.y), fmaxf(a2v.y, a3.y)) + sb[co+1];
            g_a1[(size_t)n*A1_PER + co*225 + pos]     = fmaxf(va, 0.f);
            g_a1[(size_t)n*A1_PER + (co+1)*225 + pos] = fmaxf(vb, 0.f);
        }
    }
}

// ---------------- stats0: one block per sample, warp = 8 channels ----------------
__global__ void __launch_bounds__(256) k_stats0() {
    int n = blockIdx.x;
    int warp = threadIdx.x >> 5, lane = threadIdx.x & 31;
    const float* base = g_a1 + (size_t)n*A1_PER + warp*8*225;
    float s[8], q[8];
#pragma unroll
    for (int c = 0; c < 8; c++) { s[c] = 0.f; q[c] = 0.f; }
#pragma unroll
    for (int c = 0; c < 8; c++) {
        const float* p = base + c*225;
        for (int i = lane; i < 225; i += 32) {
            float v = p[i]; s[c] += v; q[c] = fmaf(v, v, q[c]);
        }
    }
#pragma unroll
    for (int c = 0; c < 8; c++) {
        float a = wredsum(s[c]);
        float b = wredsum(q[c]);
        if (lane == 0) {
            atomicAdd(g_sum1 + warp*8 + c, a);
            atomicAdd(g_ssq1 + warp*8 + c, b);
        }
    }
}

// ---------------- conv2 v8 (unchanged, proven 334us) ----------------
#define C2P 22
__global__ void __launch_bounds__(288, 3) k_conv2(const float* __restrict__ c2b,
                                                  const float* __restrict__ bn1s,
                                                  const float* __restrict__ bn1b) {
    __shared__ __align__(16) float  sin[2*16*15*C2P];
    __shared__ __align__(16) float2 swp[16*16*10];
    __shared__ float sg1[64], sb1[64];
    __shared__ float ssum[32], sssq[32];
    int n0 = blockIdx.x * 2, tid = threadIdx.x;
    int s = tid / 144, r = tid % 144, pg = r % 36, cog = r / 36;
    int y0 = (pg / 6) * 2, x0 = (pg % 6) * 2;

    if (tid < 64) {
        float m  = g_sum1[tid] * (1.f / 460800.f);
        float vv = fmaxf(g_ssq1[tid] * (1.f / 460800.f) - m*m, 0.f);
        float gg = bn1s[tid] * rsqrtf(vv + BN_EPS);
        sg1[tid] = gg; sb1[tid] = bn1b[tid] - m * gg;
    }
    if (tid < 32) { ssum[tid] = 0.f; sssq[tid] = 0.f; }

    u64 acc[4][4];
#pragma unroll
    for (int j = 0; j < 4; j++)
#pragma unroll
        for (int p = 0; p < 4; p++) acc[j][p] = 0ull;

    for (int ch = 0; ch < 4; ch++) {
        __syncthreads();
        for (int i = tid; i < 7200; i += 288) {
            int ss = i / 3600, j = i % 3600, ci = j / 225, rem = j % 225;
            int y = rem / 15, xx = rem % 15;
            int c = ch*16 + ci;
            sin[(ss*16 + ci)*330 + y*C2P + xx] =
                fmaf(g_a1[(size_t)(n0+ss)*A1_PER + c*225 + rem], sg1[c], sb1[c]);
        }
        {
            const float4* wsrc = (const float4*)(g_w2p + (size_t)ch*2560);
            float4* wdst = (float4*)swp;
            for (int i = tid; i < 1280; i += 288) wdst[i] = wsrc[i];
        }
        __syncthreads();

        const float* sp = sin + s*16*330 + y0*C2P + x0;
#pragma unroll 2
        for (int ci = 0; ci < 16; ci++) {
            u64 pp[4][4];
#pragma unroll
            for (int rr = 0; rr < 4; rr++) {
                float2 f01 = *(const float2*)(sp + ci*330 + rr*C2P);
                float2 f23 = *(const float2*)(sp + ci*330 + rr*C2P + 2);
                pp[rr][0] = dup2(f01.x); pp[rr][1] = dup2(f01.y);
                pp[rr][2] = dup2(f23.x); pp[rr][3] = dup2(f23.y);
            }
            const ulonglong2* wv = (const ulonglong2*)(swp + (ci*16 + cog*4)*10);
#pragma unroll
            for (int j = 0; j < 4; j++) {
                ulonglong2 wa = wv[j*5+0], wb = wv[j*5+1], wc = wv[j*5+2],
                           wd = wv[j*5+3], we = wv[j*5+4];
                u64 wk[9] = {wa.x, wa.y, wb.x, wb.y, wc.x, wc.y, wd.x, wd.y, we.x};
#pragma unroll
                for (int ky = 0; ky < 3; ky++)
#pragma unroll
                    for (int kx = 0; kx < 3; kx++) {
                        u64 w = wk[ky*3+kx];
                        acc[j][0] = fma2(w, pp[ky  ][kx  ], acc[j][0]);
                        acc[j][1] = fma2(w, pp[ky  ][kx+1], acc[j][1]);
                        acc[j][2] = fma2(w, pp[ky+1][kx  ], acc[j][2]);
                        acc[j][3] = fma2(w, pp[ky+1][kx+1], acc[j][3]);
                    }
            }
        }
    }

#pragma unroll
    for (int j = 0; j < 4; j++) {
        float2 a0 = unpack2(acc[j][0]), a1v = unpack2(acc[j][1]);
        float2 a2v = unpack2(acc[j][2]), a3 = unpack2(acc[j][3]);
        int co = cog*8 + 2*j;
        float va = fmaxf(fmaxf(a0.x, a1v.x), fmaxf(a2v.x, a3.x)) + __ldg(c2b + co);
        float vb = fmaxf(fmaxf(a0.y, a1v.y), fmaxf(a2v.y, a3.y)) + __ldg(c2b + co + 1);
        va = fmaxf(va, 0.f); vb = fmaxf(vb, 0.f);
        *(float2*)(g_a2 + ((size_t)(n0+s)*36 + pg)*32 + co) = make_float2(va, vb);
        atomicAdd(&ssum[co],   va); atomicAdd(&sssq[co],   va*va);
        atomicAdd(&ssum[co+1], vb); atomicAdd(&sssq[co+1], vb*vb);
    }
    __syncthreads();
    if (tid < 32) {
        atomicAdd(g_sum2 + tid, ssum[tid]);
        atomicAdd(g_ssq2 + tid, sssq[tid]);
    }
}

// ---------------- conv3 (proven, fused BN2 coef) ----------------
#define C3_SW   0
#define C3_SIN  12288
#define C3_ST   17040
#define C3_CF   17104
#define CONV3_SMEM (17168 * 4)
__global__ void __launch_bounds__(256) k_conv3(const float* __restrict__ bias,
                                               const float* __restrict__ bn2s,
                                               const float* __restrict__ bn2b) {
    extern __shared__ __align__(16) float sm3[];
    float* sw3  = sm3 + C3_SW;
    float* sin2 = sm3 + C3_SIN;
    float* ssum = sm3 + C3_ST;
    float* sssq = sm3 + C3_ST + 32;
    float* sg2  = sm3 + C3_CF;
    float* sb2c = sm3 + C3_CF + 32;
    int n0 = blockIdx.x * 4, tid = threadIdx.x;

    if (tid < 32) {
        float m  = g_sum2[tid] * (1.f / 73728.f);
        float vv = fmaxf(g_ssq2[tid] * (1.f / 73728.f) - m*m, 0.f);
        float gg = bn2s[tid] * rsqrtf(vv + BN_EPS);
        sg2[tid] = gg; sb2c[tid] = bn2b[tid] - m * gg;
        ssum[tid] = 0.f; sssq[tid] = 0.f;
    }
    __syncthreads();

    {
        const float4* wsrc = (const float4*)g_w3p;
        float4* wdst = (float4*)sw3;
        for (int i = tid; i < 3072; i += 256) wdst[i] = wsrc[i];
    }
    for (int i = tid; i < 4608; i += 256) {
        int s = i / 1152, j = i % 1152, pos = j / 32, c = j & 31;
        sin2[s*1188 + pos*33 + c] = fmaf(g_a2[(size_t)(n0+s)*A2_PER + j], sg2[c], sb2c[c]);
    }
    __syncthreads();

    int s = tid / 64, r = tid % 64, pos = r % 16, grp = r / 16;
    int py = pos / 4, px = pos % 4;
    float acc[8];
#pragma unroll
    for (int a = 0; a < 8; a++) acc[a] = 0.f;

    const float* sb2 = sin2 + s*1188;
    for (int ci = 0; ci < 32; ci++) {
        float p[9];
#pragma unroll
        for (int ky = 0; ky < 3; ky++)
#pragma unroll
            for (int kx = 0; kx < 3; kx++) p[ky*3+kx] = sb2[((py+ky)*6 + px+kx)*33 + ci];
        const float* wb = sw3 + (ci*32 + grp*8)*12;
#pragma unroll
        for (int cl = 0; cl < 8; cl++) {
            const float4* w4 = (const float4*)(wb + cl*12);
            float4 wa = w4[0], wc = w4[1];
            float wv[9] = {wa.x, wa.y, wa.z, wa.w, wc.x, wc.y, wc.z, wc.w, wb[cl*12+8]};
            float a = acc[cl];
#pragma unroll
            for (int k = 0; k < 9; k++) a = fmaf(wv[k], p[k], a);
            acc[cl] = a;
        }
    }
#pragma unroll
    for (int cl = 0; cl < 8; cl++) {
        int co = grp*8 + cl;
        float v = fmaxf(acc[cl] + bias[co], 0.f);
        g_hp[(size_t)(n0+s)*H_PER + co*16 + pos] = v;
        atomicAdd(&ssum[co], v);
        atomicAdd(&sssq[co], v*v);
    }
    __syncthreads();
    if (tid < 32) {
        atomicAdd(g_sum3 + tid, ssum[tid]);
        atomicAdd(g_ssq3 + tid, sssq[tid]);
    }
}

// ---------------- VQ + blend + FC1 + FC2 + log_softmax (v2, proven) ----------------
__global__ void __launch_bounds__(128) k_vqfc(const float* __restrict__ cb,
                                              const float* __restrict__ fc1w,
                                              const float* __restrict__ fc1b,
                                              const float* __restrict__ fc2w,
                                              const float* __restrict__ fc2b,
                                              const float* __restrict__ bn3s,
                                              const float* __restrict__ bn3b,
                                              float* __restrict__ out) {
    __shared__ float scb[KCB*32];
    __shared__ float scbT[32*104];
    __shared__ float scbsq[KCB];
    __shared__ float hs[512];
    __shared__ float bl[512];
    __shared__ float z1[64];
    __shared__ float z1h[128];
    __shared__ int   idxs[16];
    __shared__ float wred[4];
    __shared__ float sg3[32], sb3c[32];
    int n = blockIdx.x, tid = threadIdx.x;
    unsigned full = 0xffffffffu;

    if (tid < 32) {
        float m  = g_sum3[tid] * (1.f / 32768.f);
        float vv = fmaxf(g_ssq3[tid] * (1.f / 32768.f) - m*m, 0.f);
        float gg = bn3s[tid] * rsqrtf(vv + BN_EPS);
        sg3[tid] = gg; sb3c[tid] = bn3b[tid] - m * gg;
    }
    __syncthreads();

    for (int i = tid; i < KCB*32; i += 128) {
        float v = cb[i];
        scb[i] = v;
        scbT[(i & 31)*104 + (i >> 5)] = v;
    }
    if (tid < KCB) scbsq[tid] = g_cbsq[tid];
    for (int i = tid; i < 512; i += 128) {
        int c = i >> 4;
        float v = fmaf(g_hp[(size_t)n*H_PER + i], sg3[c], sb3c[c]);
        hs[i] = v;
        out[H_OFF + (size_t)n*512 + i] = v;
    }
    __syncthreads();

    int pos = tid >> 3, sub = tid & 7;
    float z[32];
#pragma unroll
    for (int c = 0; c < 32; c++) z[c] = hs[c*16 + pos];
    float zz = 0.f;
#pragma unroll
    for (int c = 0; c < 32; c++) zz = fmaf(z[c], z[c], zz);
    float bd = INFINITY; int bi = 0;
    for (int k = sub; k < KCB; k += 8) {
        float dot = 0.f;
#pragma unroll
        for (int c = 0; c < 32; c++) dot = fmaf(scbT[c*104 + k], z[c], dot);
        float d = zz + scbsq[k] - 2.f*dot;
        if (d < bd) { bd = d; bi = k; }
    }
#pragma unroll
    for (int off = 4; off; off >>= 1) {
        float od = __shfl_down_sync(full, bd, off, 8);
        int   oi = __shfl_down_sync(full, bi, off, 8);
        if (od < bd || (od == bd && oi < bi)) { bd = od; bi = oi; }
    }
    if (sub == 0) idxs[pos] = bi;
    __syncthreads();

    float vqs = 0.f;
    for (int i = tid; i < 512; i += 128) {
        int c = i >> 4, p2 = i & 15;
        float q = scb[idxs[p2]*32 + c];
        float zv = hs[i];
        float df = q - zv;
        vqs = fmaf(df, df, vqs);
        out[RECON_OFF + (size_t)n*512 + i] = q;
        bl[i] = fmaf(0.5f, q, zv);
    }
    vqs = wredsum(vqs);
    if ((tid & 31) == 0) wred[tid >> 5] = vqs;
    __syncthreads();
    if (tid == 0) atomicAdd(&g_vq, wred[0] + wred[1] + wred[2] + wred[3]);

    {
        int o = tid & 63, hh = tid >> 6;
        const float4* wp4 = (const float4*)(fc1w + o*512 + hh*256);
        const float4* bl4 = (const float4*)(bl + hh*256);
        float a = 0.f;
#pragma unroll 8
        for (int t = 0; t < 64; t++) {
            float4 w = wp4[t], b = bl4[t];
            a = fmaf(w.x, b.x, a); a = fmaf(w.y, b.y, a);
            a = fmaf(w.z, b.z, a); a = fmaf(w.w, b.w, a);
        }
        z1h[tid] = a;
    }
    __syncthreads();
    if (tid < 64) z1[tid] = fmaxf(z1h[tid] + z1h[64 + tid] + fc1b[tid], 0.f);
    __syncthreads();

    if (tid < 32) {
        int lane = tid;
        float y = -INFINITY;
        if (lane < 10) {
            const float* wp = fc2w + lane*64;
            float a = 0.f;
#pragma unroll
            for (int j = 0; j < 64; j++) a = fmaf(wp[j], z1[j], a);
            y = a + fc2b[lane];
        }
        float m = y;
#pragma unroll
        for (int off = 16; off; off >>= 1) m = fmaxf(m, __shfl_xor_sync(full, m, off));
        float e = (lane < 10) ? expf(y - m) : 0.f;
        float ssum = e;
#pragma unroll
        for (int off = 16; off; off >>= 1) ssum += __shfl_xor_sync(full, ssum, off);
        if (lane < 10) out[LP_OFF + (size_t)n*10 + lane] = y - m - logf(ssum);
    }
}

__global__ void k_final(float* __restrict__ out) {
    out[LOSS_OFF] = 1.25f * g_vq / (float)(B * 16 * 32);
}

// ---------------- launch ----------------
extern "C" void kernel_launch(void* const* d_in, const int* in_sizes, int n_in,
                              void* d_out, int out_size) {
    const float* x      = (const float*)d_in[0];
    const float* c1w    = (const float*)d_in[1];
    const float* c1b    = (const float*)d_in[2];
    const float* bn1s   = (const float*)d_in[3];
    const float* bn1b   = (const float*)d_in[4];
    const float* c2w    = (const float*)d_in[5];
    const float* c2b    = (const float*)d_in[6];
    const float* bn2s   = (const float*)d_in[7];
    const float* bn2b   = (const float*)d_in[8];
    const float* c3w    = (const float*)d_in[9];
    const float* c3b    = (const float*)d_in[10];
    const float* bn3s   = (const float*)d_in[11];
    const float* bn3b   = (const float*)d_in[12];
    const float* cb     = (const float*)d_in[13];
    const float* fc1w   = (const float*)d_in[14];
    const float* fc1b   = (const float*)d_in[15];
    const float* fc2w   = (const float*)d_in[16];
    const float* fc2b   = (const float*)d_in[17];
    float* out = (float*)d_out;

    cudaFuncSetAttribute(k_conv3, cudaFuncAttributeMaxDynamicSharedMemorySize, CONV3_SMEM);

    k_setup<<<48, 256>>>(cb, c1w, c2w, c3w);                       // 0
    k_conv1<<<B, 256>>>(x, c1b);                                   // 1
    k_stats0<<<B, 256>>>();                                        // 2
    k_conv2<<<B/2, 288>>>(c2b, bn1s, bn1b);                        // 3  <- ncu capture (sanity: ~334us)
    k_conv3<<<B/4, 256, CONV3_SMEM>>>(c3b, bn2s, bn2b);            // 4
    k_vqfc<<<B, 128>>>(cb, fc1w, fc1b, fc2w, fc2b, bn3s, bn3b, out); // 5
    k_final<<<1, 1>>>(out);                                        // 6
}

// round 12
// speedup vs baseline: 1.1417x; 1.0163x over previous
#include <cuda_runtime.h>
#include <math.h>

#define B 2048
#define A1_PER (64*225)       // 14400
#define A2_PER (32*36)        // 1152
#define H_PER 512
#define KCB 100
#define BN_EPS 1e-5f

#define RECON_OFF 0
#define H_OFF     (B*H_PER)
#define LOSS_OFF  (2*B*H_PER)
#define LP_OFF    (2*B*H_PER + 1)

typedef unsigned long long u64;

// ---------------- device scratch ----------------
__device__ __align__(16) float g_a1[B*A1_PER];   // conv1 out [n][co][225] (pre-BN)
__device__ __align__(16) float g_a2[B*A2_PER];   // conv2 out [n][pos36][co32]
__device__ __align__(16) float g_hp[B*H_PER];    // conv3 out [n][co][16]
__device__ __align__(16) float2 g_w1p[3*64*10];  // conv1 co-pairs [ci][cp32][10] (960 used)
__device__ __align__(16) float2 g_w2p[64*16*10]; // conv2 co-pairs [ci][cp][10]
__device__ __align__(16) float  g_w3p[32*32*12]; // conv3 [ci][co][12]
__device__ float g_sum1[64], g_ssq1[64];
__device__ float g_sum2[32], g_ssq2[32];
__device__ float g_sum3[32], g_ssq3[32];
__device__ float g_cbsq[KCB];
__device__ float g_vq;

__device__ __forceinline__ float wredsum(float v) {
#pragma unroll
    for (int o = 16; o; o >>= 1) v += __shfl_down_sync(0xffffffffu, v, o);
    return v;
}
__device__ __forceinline__ u64 pack2(float x, float y) {
    u64 r; asm("mov.b64 %0, {%1,%2};" : "=l"(r) : "f"(x), "f"(y)); return r;
}
__device__ __forceinline__ u64 dup2(float x) { return pack2(x, x); }
__device__ __forceinline__ u64 fma2(u64 a, u64 b, u64 c) {
    u64 d; asm("fma.rn.f32x2 %0, %1, %2, %3;" : "=l"(d) : "l"(a), "l"(b), "l"(c)); return d;
}
__device__ __forceinline__ float2 unpack2(u64 a) {
    float2 f; asm("mov.b64 {%0,%1}, %2;" : "=f"(f.x), "=f"(f.y) : "l"(a)); return f;
}

// ---------------- setup: init + weight repack ----------------
__global__ void k_setup(const float* __restrict__ cb, const float* __restrict__ w1,
                        const float* __restrict__ w2, const float* __restrict__ w3) {
    int t = blockIdx.x * blockDim.x + threadIdx.x;
    if (t < 64) { g_sum1[t] = 0.f; g_ssq1[t] = 0.f; }
    if (t < 32) { g_sum2[t] = 0.f; g_ssq2[t] = 0.f; g_sum3[t] = 0.f; g_ssq3[t] = 0.f; }
    if (t == 0) g_vq = 0.f;
    if (t < KCB) {
        float s = 0.f;
#pragma unroll
        for (int c = 0; c < 32; c++) { float v = cb[t*32+c]; s = fmaf(v, v, s); }
        g_cbsq[t] = s;
    }
    if (t < 960) {                        // conv1 co-pairs [ci][cp32][10]
        int k = t % 10, r = t / 10, ci = r / 32, cp = r % 32;
        float a = 0.f, b = 0.f;
        if (k < 9) { a = w1[(2*cp)*27 + ci*9 + k]; b = w1[(2*cp+1)*27 + ci*9 + k]; }
        g_w1p[t] = make_float2(a, b);
    }
    if (t < 10240) {                      // conv2 co-pairs [ci][cp][10]
        int k = t % 10, r = t / 10, ci = r / 16, cp = r % 16;
        float a = 0.f, b = 0.f;
        if (k < 9) { a = w2[(2*cp)*576 + ci*9 + k]; b = w2[(2*cp+1)*576 + ci*9 + k]; }
        g_w2p[t] = make_float2(a, b);
    }
    if (t < 12288) {                      // conv3 [ci][co][12]
        int k = t % 12, r = t / 12, ci = r / 32, co = r % 32;
        g_w3p[t] = (k < 9) ? w3[co*288 + ci*9 + k] : 0.f;
    }
}

// ---------------- conv1 v2 (proven, ~122us) ----------------
__global__ void __launch_bounds__(256, 3) k_conv1(const float* __restrict__ x,
                                                  const float* __restrict__ bias) {
    __shared__ __align__(16) float  sx[3*32*34];
    __shared__ __align__(16) float2 swp1[3*32*10];
    __shared__ float sb[64];
    int n = blockIdx.x, tid = threadIdx.x;

    const float4* x4 = (const float4*)(x + (size_t)n * 3072);
    for (int i = tid; i < 768; i += 256) {
        float4 v = x4[i];
        int e = i * 4, ci = e >> 10, rem = e & 1023, y = rem >> 5, xc = rem & 31;
        float* d = sx + ci*1088 + y*34 + xc;
        d[0] = v.x; d[1] = v.y; d[2] = v.z; d[3] = v.w;
    }
    {
        const float4* wsrc = (const float4*)g_w1p;
        float4* wdst = (float4*)swp1;
        for (int i = tid; i < 480; i += 256) wdst[i] = wsrc[i];
    }
    if (tid < 64) sb[tid] = bias[tid];
    __syncthreads();

    for (int it = tid; it < 1800; it += 256) {
        int pos = it % 225, cg = it / 225;
        int py2 = (pos / 15) * 2, px2 = (pos % 15) * 2;
        u64 acc[4][4];
#pragma unroll
        for (int j = 0; j < 4; j++)
#pragma unroll
            for (int p = 0; p < 4; p++) acc[j][p] = 0ull;

#pragma unroll
        for (int ci = 0; ci < 3; ci++) {
            const float* sp = sx + ci*1088 + py2*34 + px2;
            u64 pp[4][4];
#pragma unroll
            for (int rr = 0; rr < 4; rr++) {
                float2 f01 = *(const float2*)(sp + rr*34);
                float2 f23 = *(const float2*)(sp + rr*34 + 2);
                pp[rr][0] = dup2(f01.x); pp[rr][1] = dup2(f01.y);
                pp[rr][2] = dup2(f23.x); pp[rr][3] = dup2(f23.y);
            }
            const ulonglong2* wv = (const ulonglong2*)(swp1 + (ci*32 + cg*4)*10);
#pragma unroll
            for (int j = 0; j < 4; j++) {
                ulonglong2 wa = wv[j*5+0], wb = wv[j*5+1], wc = wv[j*5+2],
                           wd = wv[j*5+3], we = wv[j*5+4];
                u64 wk[9] = {wa.x, wa.y, wb.x, wb.y, wc.x, wc.y, wd.x, wd.y, we.x};
#pragma unroll
                for (int ky = 0; ky < 3; ky++)
#pragma unroll
                    for (int kx = 0; kx < 3; kx++) {
                        u64 w = wk[ky*3+kx];
                        acc[j][0] = fma2(w, pp[ky  ][kx  ], acc[j][0]);
                        acc[j][1] = fma2(w, pp[ky  ][kx+1], acc[j][1]);
                        acc[j][2] = fma2(w, pp[ky+1][kx  ], acc[j][2]);
                        acc[j][3] = fma2(w, pp[ky+1][kx+1], acc[j][3]);
                    }
            }
        }
#pragma unroll
        for (int j = 0; j < 4; j++) {
            float2 a0 = unpack2(acc[j][0]), a1v = unpack2(acc[j][1]);
            float2 a2v = unpack2(acc[j][2]), a3 = unpack2(acc[j][3]);
            int co = cg*8 + 2*j;
            float va = fmaxf(fmaxf(a0.x, a1v.x), fmaxf(a2v.x, a3.x)) + sb[co];
            float vb = fmaxf(fmaxf(a0.y, a1v.y), fmaxf(a2v.y, a3.y)) + sb[co+1];
            g_a1[(size_t)n*A1_PER + co*225 + pos]     = fmaxf(va, 0.f);
            g_a1[(size_t)n*A1_PER + (co+1)*225 + pos] = fmaxf(vb, 0.f);
        }
    }
}

// ---------------- stats0: one block per sample, warp = 8 channels ----------------
__global__ void __launch_bounds__(256) k_stats0() {
    int n = blockIdx.x;
    int warp = threadIdx.x >> 5, lane = threadIdx.x & 31;
    const float* base = g_a1 + (size_t)n*A1_PER + warp*8*225;
    float s[8], q[8];
#pragma unroll
    for (int c = 0; c < 8; c++) { s[c] = 0.f; q[c] = 0.f; }
#pragma unroll
    for (int c = 0; c < 8; c++) {
        const float* p = base + c*225;
        for (int i = lane; i < 225; i += 32) {
            float v = p[i]; s[c] += v; q[c] = fmaf(v, v, q[c]);
        }
    }
#pragma unroll
    for (int c = 0; c < 8; c++) {
        float a = wredsum(s[c]);
        float b = wredsum(q[c]);
        if (lane == 0) {
            atomicAdd(g_sum1 + warp*8 + c, a);
            atomicAdd(g_ssq1 + warp*8 + c, b);
        }
    }
}

// ---------------- conv2 v9: 576 threads, 2 co-pairs/thread, 2 blocks/SM ----------------
// thread = (s 0..1, pg 0..35, cog 0..7); 4 co per thread, acc = 8 u64
#define C2P 22
__global__ void __launch_bounds__(576, 2) k_conv2(const float* __restrict__ c2b,
                                                  const float* __restrict__ bn1s,
                                                  const float* __restrict__ bn1b) {
    __shared__ __align__(16) float  sin[2*16*15*C2P];   // [s][ci][y:15][x pitch22]
    __shared__ __align__(16) float2 swp[16*16*10];      // [ci][cp][10]
    __shared__ float sg1[64], sb1[64];
    __shared__ float ssum[32], sssq[32];
    int n0 = blockIdx.x * 2, tid = threadIdx.x;
    int s = tid / 288, r = tid % 288, pg = r % 36, cog = r / 36;   // cog 0..7
    int y0 = (pg / 6) * 2, x0 = (pg % 6) * 2;

    if (tid < 64) {
        float m  = g_sum1[tid] * (1.f / 460800.f);
        float vv = fmaxf(g_ssq1[tid] * (1.f / 460800.f) - m*m, 0.f);
        float gg = bn1s[tid] * rsqrtf(vv + BN_EPS);
        sg1[tid] = gg; sb1[tid] = bn1b[tid] - m * gg;
    }
    if (tid < 32) { ssum[tid] = 0.f; sssq[tid] = 0.f; }

    u64 acc[2][4];                                      // [pair j][pos]
#pragma unroll
    for (int j = 0; j < 2; j++)
#pragma unroll
        for (int p = 0; p < 4; p++) acc[j][p] = 0ull;

    for (int ch = 0; ch < 4; ch++) {
        __syncthreads();
        for (int i = tid; i < 7200; i += 576) {
            int ss = i / 3600, j = i % 3600, ci = j / 225, rem = j % 225;
            int y = rem / 15, xx = rem % 15;
            int c = ch*16 + ci;
            sin[(ss*16 + ci)*330 + y*C2P + xx] =
                fmaf(g_a1[(size_t)(n0+ss)*A1_PER + c*225 + rem], sg1[c], sb1[c]);
        }
        {
            const float4* wsrc = (const float4*)(g_w2p + (size_t)ch*2560);
            float4* wdst = (float4*)swp;
            for (int i = tid; i < 1280; i += 576) wdst[i] = wsrc[i];
        }
        __syncthreads();

        const float* sp = sin + s*16*330 + y0*C2P + x0;
#pragma unroll 2
        for (int ci = 0; ci < 16; ci++) {
            u64 pp[4][4];
#pragma unroll
            for (int rr = 0; rr < 4; rr++) {
                float2 f01 = *(const float2*)(sp + ci*330 + rr*C2P);
                float2 f23 = *(const float2*)(sp + ci*330 + rr*C2P + 2);
                pp[rr][0] = dup2(f01.x); pp[rr][1] = dup2(f01.y);
                pp[rr][2] = dup2(f23.x); pp[rr][3] = dup2(f23.y);
            }
            const ulonglong2* wv = (const ulonglong2*)(swp + (ci*16 + cog*2)*10);
#pragma unroll
            for (int j = 0; j < 2; j++) {
                ulonglong2 wa = wv[j*5+0], wb = wv[j*5+1], wc = wv[j*5+2],
                           wd = wv[j*5+3], we = wv[j*5+4];
                u64 wk[9] = {wa.x, wa.y, wb.x, wb.y, wc.x, wc.y, wd.x, wd.y, we.x};
#pragma unroll
                for (int ky = 0; ky < 3; ky++)
#pragma unroll
                    for (int kx = 0; kx < 3; kx++) {
                        u64 w = wk[ky*3+kx];
                        acc[j][0] = fma2(w, pp[ky  ][kx  ], acc[j][0]);
                        acc[j][1] = fma2(w, pp[ky  ][kx+1], acc[j][1]);
                        acc[j][2] = fma2(w, pp[ky+1][kx  ], acc[j][2]);
                        acc[j][3] = fma2(w, pp[ky+1][kx+1], acc[j][3]);
                    }
            }
        }
    }

    // epilogue: pool in regs, bias, relu, write float2, stats
#pragma unroll
    for (int j = 0; j < 2; j++) {
        float2 a0 = unpack2(acc[j][0]), a1v = unpack2(acc[j][1]);
        float2 a2v = unpack2(acc[j][2]), a3 = unpack2(acc[j][3]);
        int co = cog*4 + 2*j;
        float va = fmaxf(fmaxf(a0.x, a1v.x), fmaxf(a2v.x, a3.x)) + __ldg(c2b + co);
        float vb = fmaxf(fmaxf(a0.y, a1v.y), fmaxf(a2v.y, a3.y)) + __ldg(c2b + co + 1);
        va = fmaxf(va, 0.f); vb = fmaxf(vb, 0.f);
        *(float2*)(g_a2 + ((size_t)(n0+s)*36 + pg)*32 + co) = make_float2(va, vb);
        atomicAdd(&ssum[co],   va); atomicAdd(&sssq[co],   va*va);
        atomicAdd(&ssum[co+1], vb); atomicAdd(&sssq[co+1], vb*vb);
    }
    __syncthreads();
    if (tid < 32) {
        atomicAdd(g_sum2 + tid, ssum[tid]);
        atomicAdd(g_ssq2 + tid, sssq[tid]);
    }
}

// ---------------- conv3 (proven, fused BN2 coef) ----------------
#define C3_SW   0
#define C3_SIN  12288
#define C3_ST   17040
#define C3_CF   17104
#define CONV3_SMEM (17168 * 4)
__global__ void __launch_bounds__(256) k_conv3(const float* __restrict__ bias,
                                               const float* __restrict__ bn2s,
                                               const float* __restrict__ bn2b) {
    extern __shared__ __align__(16) float sm3[];
    float* sw3  = sm3 + C3_SW;
    float* sin2 = sm3 + C3_SIN;
    float* ssum = sm3 + C3_ST;
    float* sssq = sm3 + C3_ST + 32;
    float* sg2  = sm3 + C3_CF;
    float* sb2c = sm3 + C3_CF + 32;
    int n0 = blockIdx.x * 4, tid = threadIdx.x;

    if (tid < 32) {
        float m  = g_sum2[tid] * (1.f / 73728.f);
        float vv = fmaxf(g_ssq2[tid] * (1.f / 73728.f) - m*m, 0.f);
        float gg = bn2s[tid] * rsqrtf(vv + BN_EPS);
        sg2[tid] = gg; sb2c[tid] = bn2b[tid] - m * gg;
        ssum[tid] = 0.f; sssq[tid] = 0.f;
    }
    __syncthreads();

    {
        const float4* wsrc = (const float4*)g_w3p;
        float4* wdst = (float4*)sw3;
        for (int i = tid; i < 3072; i += 256) wdst[i] = wsrc[i];
    }
    for (int i = tid; i < 4608; i += 256) {
        int s = i / 1152, j = i % 1152, pos = j / 32, c = j & 31;
        sin2[s*1188 + pos*33 + c] = fmaf(g_a2[(size_t)(n0+s)*A2_PER + j], sg2[c], sb2c[c]);
    }
    __syncthreads();

    int s = tid / 64, r = tid % 64, pos = r % 16, grp = r / 16;
    int py = pos / 4, px = pos % 4;
    float acc[8];
#pragma unroll
    for (int a = 0; a < 8; a++) acc[a] = 0.f;

    const float* sb2 = sin2 + s*1188;
    for (int ci = 0; ci < 32; ci++) {
        float p[9];
#pragma unroll
        for (int ky = 0; ky < 3; ky++)
#pragma unroll
            for (int kx = 0; kx < 3; kx++) p[ky*3+kx] = sb2[((py+ky)*6 + px+kx)*33 + ci];
        const float* wb = sw3 + (ci*32 + grp*8)*12;
#pragma unroll
        for (int cl = 0; cl < 8; cl++) {
            const float4* w4 = (const float4*)(wb + cl*12);
            float4 wa = w4[0], wc = w4[1];
            float wv[9] = {wa.x, wa.y, wa.z, wa.w, wc.x, wc.y, wc.z, wc.w, wb[cl*12+8]};
            float a = acc[cl];
#pragma unroll
            for (int k = 0; k < 9; k++) a = fmaf(wv[k], p[k], a);
            acc[cl] = a;
        }
    }
#pragma unroll
    for (int cl = 0; cl < 8; cl++) {
        int co = grp*8 + cl;
        float v = fmaxf(acc[cl] + bias[co], 0.f);
        g_hp[(size_t)(n0+s)*H_PER + co*16 + pos] = v;
        atomicAdd(&ssum[co], v);
        atomicAdd(&sssq[co], v*v);
    }
    __syncthreads();
    if (tid < 32) {
        atomicAdd(g_sum3 + tid, ssum[tid]);
        atomicAdd(g_ssq3 + tid, sssq[tid]);
    }
}

// ---------------- VQ + blend + FC1 + FC2 + log_softmax (v2, proven) ----------------
__global__ void __launch_bounds__(128) k_vqfc(const float* __restrict__ cb,
                                              const float* __restrict__ fc1w,
                                              const float* __restrict__ fc1b,
                                              const float* __restrict__ fc2w,
                                              const float* __restrict__ fc2b,
                                              const float* __restrict__ bn3s,
                                              const float* __restrict__ bn3b,
                                              float* __restrict__ out) {
    __shared__ float scb[KCB*32];
    __shared__ float scbT[32*104];
    __shared__ float scbsq[KCB];
    __shared__ float hs[512];
    __shared__ float bl[512];
    __shared__ float z1[64];
    __shared__ float z1h[128];
    __shared__ int   idxs[16];
    __shared__ float wred[4];
    __shared__ float sg3[32], sb3c[32];
    int n = blockIdx.x, tid = threadIdx.x;
    unsigned full = 0xffffffffu;

    if (tid < 32) {
        float m  = g_sum3[tid] * (1.f / 32768.f);
        float vv = fmaxf(g_ssq3[tid] * (1.f / 32768.f) - m*m, 0.f);
        float gg = bn3s[tid] * rsqrtf(vv + BN_EPS);
        sg3[tid] = gg; sb3c[tid] = bn3b[tid] - m * gg;
    }
    __syncthreads();

    for (int i = tid; i < KCB*32; i += 128) {
        float v = cb[i];
        scb[i] = v;
        scbT[(i & 31)*104 + (i >> 5)] = v;
    }
    if (tid < KCB) scbsq[tid] = g_cbsq[tid];
    for (int i = tid; i < 512; i += 128) {
        int c = i >> 4;
        float v = fmaf(g_hp[(size_t)n*H_PER + i], sg3[c], sb3c[c]);
        hs[i] = v;
        out[H_OFF + (size_t)n*512 + i] = v;
    }
    __syncthreads();

    int pos = tid >> 3, sub = tid & 7;
    float z[32];
#pragma unroll
    for (int c = 0; c < 32; c++) z[c] = hs[c*16 + pos];
    float zz = 0.f;
#pragma unroll
    for (int c = 0; c < 32; c++) zz = fmaf(z[c], z[c], zz);
    float bd = INFINITY; int bi = 0;
    for (int k = sub; k < KCB; k += 8) {
        float dot = 0.f;
#pragma unroll
        for (int c = 0; c < 32; c++) dot = fmaf(scbT[c*104 + k], z[c], dot);
        float d = zz + scbsq[k] - 2.f*dot;
        if (d < bd) { bd = d; bi = k; }
    }
#pragma unroll
    for (int off = 4; off; off >>= 1) {
        float od = __shfl_down_sync(full, bd, off, 8);
        int   oi = __shfl_down_sync(full, bi, off, 8);
        if (od < bd || (od == bd && oi < bi)) { bd = od; bi = oi; }
    }
    if (sub == 0) idxs[pos] = bi;
    __syncthreads();

    float vqs = 0.f;
    for (int i = tid; i < 512; i += 128) {
        int c = i >> 4, p2 = i & 15;
        float q = scb[idxs[p2]*32 + c];
        float zv = hs[i];
        float df = q - zv;
        vqs = fmaf(df, df, vqs);
        out[RECON_OFF + (size_t)n*512 + i] = q;
        bl[i] = fmaf(0.5f, q, zv);
    }
    vqs = wredsum(vqs);
    if ((tid & 31) == 0) wred[tid >> 5] = vqs;
    __syncthreads();
    if (tid == 0) atomicAdd(&g_vq, wred[0] + wred[1] + wred[2] + wred[3]);

    {
        int o = tid & 63, hh = tid >> 6;
        const float4* wp4 = (const float4*)(fc1w + o*512 + hh*256);
        const float4* bl4 = (const float4*)(bl + hh*256);
        float a = 0.f;
#pragma unroll 8
        for (int t = 0; t < 64; t++) {
            float4 w = wp4[t], b = bl4[t];
            a = fmaf(w.x, b.x, a); a = fmaf(w.y, b.y, a);
            a = fmaf(w.z, b.z, a); a = fmaf(w.w, b.w, a);
        }
        z1h[tid] = a;
    }
    __syncthreads();
    if (tid < 64) z1[tid] = fmaxf(z1h[tid] + z1h[64 + tid] + fc1b[tid], 0.f);
    __syncthreads();

    if (tid < 32) {
        int lane = tid;
        float y = -INFINITY;
        if (lane < 10) {
            const float* wp = fc2w + lane*64;
            float a = 0.f;
#pragma unroll
            for (int j = 0; j < 64; j++) a = fmaf(wp[j], z1[j], a);
            y = a + fc2b[lane];
        }
        float m = y;
#pragma unroll
        for (int off = 16; off; off >>= 1) m = fmaxf(m, __shfl_xor_sync(full, m, off));
        float e = (lane < 10) ? expf(y - m) : 0.f;
        float ssum = e;
#pragma unroll
        for (int off = 16; off; off >>= 1) ssum += __shfl_xor_sync(full, ssum, off);
        if (lane < 10) out[LP_OFF + (size_t)n*10 + lane] = y - m - logf(ssum);
    }
}

__global__ void k_final(float* __restrict__ out) {
    out[LOSS_OFF] = 1.25f * g_vq / (float)(B * 16 * 32);
}

// ---------------- launch ----------------
extern "C" void kernel_launch(void* const* d_in, const int* in_sizes, int n_in,
                              void* d_out, int out_size) {
    const float* x      = (const float*)d_in[0];
    const float* c1w    = (const float*)d_in[1];
    const float* c1b    = (const float*)d_in[2];
    const float* bn1s   = (const float*)d_in[3];
    const float* bn1b   = (const float*)d_in[4];
    const float* c2w    = (const float*)d_in[5];
    const float* c2b    = (const float*)d_in[6];
    const float* bn2s   = (const float*)d_in[7];
    const float* bn2b   = (const float*)d_in[8];
    const float* c3w    = (const float*)d_in[9];
    const float* c3b    = (const float*)d_in[10];
    const float* bn3s   = (const float*)d_in[11];
    const float* bn3b   = (const float*)d_in[12];
    const float* cb     = (const float*)d_in[13];
    const float* fc1w   = (const float*)d_in[14];
    const float* fc1b   = (const float*)d_in[15];
    const float* fc2w   = (const float*)d_in[16];
    const float* fc2b   = (const float*)d_in[17];
    float* out = (float*)d_out;

    cudaFuncSetAttribute(k_conv3, cudaFuncAttributeMaxDynamicSharedMemorySize, CONV3_SMEM);

    k_setup<<<48, 256>>>(cb, c1w, c2w, c3w);                       // 0
    k_conv1<<<B, 256>>>(x, c1b);                                   // 1
    k_stats0<<<B, 256>>>();                                        // 2
    k_conv2<<<B/2, 576>>>(c2b, bn1s, bn1b);                        // 3  <- ncu capture
    k_conv3<<<B/4, 256, CONV3_SMEM>>>(c3b, bn2s, bn2b);            // 4
    k_vqfc<<<B, 128>>>(cb, fc1w, fc1b, fc2w, fc2b, bn3s, bn3b, out); // 5
    k_final<<<1, 1>>>(out);                                        // 6
}

// round 13
// speedup vs baseline: 1.2007x; 1.0517x over previous
#include <cuda_runtime.h>
#include <math.h>

#define B 2048
#define A1_PER (64*225)       // 14400
#define A2_PER (32*36)        // 1152
#define H_PER 512
#define KCB 100
#define BN_EPS 1e-5f

#define RECON_OFF 0
#define H_OFF     (B*H_PER)
#define LOSS_OFF  (2*B*H_PER)
#define LP_OFF    (2*B*H_PER + 1)

typedef unsigned long long u64;

// ---------------- device scratch ----------------
__device__ __align__(16) float g_a1[B*A1_PER];   // conv1 out [n][co][225] (pre-BN)
__device__ __align__(16) float g_a2[B*A2_PER];   // conv2 out [n][pos36][co32]
__device__ __align__(16) float g_hp[B*H_PER];    // conv3 out [n][co][16]
__device__ __align__(16) float2 g_w1p[3*64*10];  // conv1 co-pairs [ci][cp32][10] (960 used)
__device__ __align__(16) float2 g_w2p[64*16*10]; // conv2 co-pairs [ci][cp][10]
__device__ __align__(16) float  g_w3p[32*32*12]; // conv3 [ci][co][12]
__device__ float g_sum1[64], g_ssq1[64];
__device__ float g_sum2[32], g_ssq2[32];
__device__ float g_sum3[32], g_ssq3[32];
__device__ float g_cbsq[KCB];
__device__ float g_vq;

__device__ __forceinline__ float wredsum(float v) {
#pragma unroll
    for (int o = 16; o; o >>= 1) v += __shfl_down_sync(0xffffffffu, v, o);
    return v;
}
__device__ __forceinline__ u64 pack2(float x, float y) {
    u64 r; asm("mov.b64 %0, {%1,%2};" : "=l"(r) : "f"(x), "f"(y)); return r;
}
__device__ __forceinline__ u64 dup2(float x) { return pack2(x, x); }
__device__ __forceinline__ u64 fma2(u64 a, u64 b, u64 c) {
    u64 d; asm("fma.rn.f32x2 %0, %1, %2, %3;" : "=l"(d) : "l"(a), "l"(b), "l"(c)); return d;
}
__device__ __forceinline__ float2 unpack2(u64 a) {
    float2 f; asm("mov.b64 {%0,%1}, %2;" : "=f"(f.x), "=f"(f.y) : "l"(a)); return f;
}

// ---------------- setup: init + weight repack ----------------
__global__ void k_setup(const float* __restrict__ cb, const float* __restrict__ w1,
                        const float* __restrict__ w2, const float* __restrict__ w3) {
    int t = blockIdx.x * blockDim.x + threadIdx.x;
    if (t < 64) { g_sum1[t] = 0.f; g_ssq1[t] = 0.f; }
    if (t < 32) { g_sum2[t] = 0.f; g_ssq2[t] = 0.f; g_sum3[t] = 0.f; g_ssq3[t] = 0.f; }
    if (t == 0) g_vq = 0.f;
    if (t < KCB) {
        float s = 0.f;
#pragma unroll
        for (int c = 0; c < 32; c++) { float v = cb[t*32+c]; s = fmaf(v, v, s); }
        g_cbsq[t] = s;
    }
    if (t < 960) {                        // conv1 co-pairs [ci][cp32][10]
        int k = t % 10, r = t / 10, ci = r / 32, cp = r % 32;
        float a = 0.f, b = 0.f;
        if (k < 9) { a = w1[(2*cp)*27 + ci*9 + k]; b = w1[(2*cp+1)*27 + ci*9 + k]; }
        g_w1p[t] = make_float2(a, b);
    }
    if (t < 10240) {                      // conv2 co-pairs [ci][cp][10]
        int k = t % 10, r = t / 10, ci = r / 16, cp = r % 16;
        float a = 0.f, b = 0.f;
        if (k < 9) { a = w2[(2*cp)*576 + ci*9 + k]; b = w2[(2*cp+1)*576 + ci*9 + k]; }
        g_w2p[t] = make_float2(a, b);
    }
    if (t < 12288) {                      // conv3 [ci][co][12]
        int k = t % 12, r = t / 12, ci = r / 32, co = r % 32;
        g_w3p[t] = (k < 9) ? w3[co*288 + ci*9 + k] : 0.f;
    }
}

// ---------------- conv1 v2 (proven, ~122us) ----------------
__global__ void __launch_bounds__(256, 3) k_conv1(const float* __restrict__ x,
                                                  const float* __restrict__ bias) {
    __shared__ __align__(16) float  sx[3*32*34];
    __shared__ __align__(16) float2 swp1[3*32*10];
    __shared__ float sb[64];
    int n = blockIdx.x, tid = threadIdx.x;

    const float4* x4 = (const float4*)(x + (size_t)n * 3072);
    for (int i = tid; i < 768; i += 256) {
        float4 v = x4[i];
        int e = i * 4, ci = e >> 10, rem = e & 1023, y = rem >> 5, xc = rem & 31;
        float* d = sx + ci*1088 + y*34 + xc;
        d[0] = v.x; d[1] = v.y; d[2] = v.z; d[3] = v.w;
    }
    {
        const float4* wsrc = (const float4*)g_w1p;
        float4* wdst = (float4*)swp1;
        for (int i = tid; i < 480; i += 256) wdst[i] = wsrc[i];
    }
    if (tid < 64) sb[tid] = bias[tid];
    __syncthreads();

    for (int it = tid; it < 1800; it += 256) {
        int pos = it % 225, cg = it / 225;
        int py2 = (pos / 15) * 2, px2 = (pos % 15) * 2;
        u64 acc[4][4];
#pragma unroll
        for (int j = 0; j < 4; j++)
#pragma unroll
            for (int p = 0; p < 4; p++) acc[j][p] = 0ull;

#pragma unroll
        for (int ci = 0; ci < 3; ci++) {
            const float* sp = sx + ci*1088 + py2*34 + px2;
            u64 pp[4][4];
#pragma unroll
            for (int rr = 0; rr < 4; rr++) {
                float2 f01 = *(const float2*)(sp + rr*34);
                float2 f23 = *(const float2*)(sp + rr*34 + 2);
                pp[rr][0] = dup2(f01.x); pp[rr][1] = dup2(f01.y);
                pp[rr][2] = dup2(f23.x); pp[rr][3] = dup2(f23.y);
            }
            const ulonglong2* wv = (const ulonglong2*)(swp1 + (ci*32 + cg*4)*10);
#pragma unroll
            for (int j = 0; j < 4; j++) {
                ulonglong2 wa = wv[j*5+0], wb = wv[j*5+1], wc = wv[j*5+2],
                           wd = wv[j*5+3], we = wv[j*5+4];
                u64 wk[9] = {wa.x, wa.y, wb.x, wb.y, wc.x, wc.y, wd.x, wd.y, we.x};
#pragma unroll
                for (int ky = 0; ky < 3; ky++)
#pragma unroll
                    for (int kx = 0; kx < 3; kx++) {
                        u64 w = wk[ky*3+kx];
                        acc[j][0] = fma2(w, pp[ky  ][kx  ], acc[j][0]);
                        acc[j][1] = fma2(w, pp[ky  ][kx+1], acc[j][1]);
                        acc[j][2] = fma2(w, pp[ky+1][kx  ], acc[j][2]);
                        acc[j][3] = fma2(w, pp[ky+1][kx+1], acc[j][3]);
                    }
            }
        }
#pragma unroll
        for (int j = 0; j < 4; j++) {
            float2 a0 = unpack2(acc[j][0]), a1v = unpack2(acc[j][1]);
            float2 a2v = unpack2(acc[j][2]), a3 = unpack2(acc[j][3]);
            int co = cg*8 + 2*j;
            float va = fmaxf(fmaxf(a0.x, a1v.x), fmaxf(a2v.x, a3.x)) + sb[co];
            float vb = fmaxf(fmaxf(a0.y, a1v.y), fmaxf(a2v.y, a3.y)) + sb[co+1];
            g_a1[(size_t)n*A1_PER + co*225 + pos]     = fmaxf(va, 0.f);
            g_a1[(size_t)n*A1_PER + (co+1)*225 + pos] = fmaxf(vb, 0.f);
        }
    }
}

// ---------------- stats0: one block per sample, warp = 8 channels ----------------
__global__ void __launch_bounds__(256) k_stats0() {
    int n = blockIdx.x;
    int warp = threadIdx.x >> 5, lane = threadIdx.x & 31;
    const float* base = g_a1 + (size_t)n*A1_PER + warp*8*225;
    float s[8], q[8];
#pragma unroll
    for (int c = 0; c < 8; c++) { s[c] = 0.f; q[c] = 0.f; }
#pragma unroll
    for (int c = 0; c < 8; c++) {
        const float* p = base + c*225;
        for (int i = lane; i < 225; i += 32) {
            float v = p[i]; s[c] += v; q[c] = fmaf(v, v, q[c]);
        }
    }
#pragma unroll
    for (int c = 0; c < 8; c++) {
        float a = wredsum(s[c]);
        float b = wredsum(q[c]);
        if (lane == 0) {
            atomicAdd(g_sum1 + warp*8 + c, a);
            atomicAdd(g_ssq1 + warp*8 + c, b);
        }
    }
}

// ---------------- conv2 v10: 576 thr, 2 co-pairs/thread, column staging ----------------
#define C2P 22
__global__ void __launch_bounds__(576, 2) k_conv2(const float* __restrict__ c2b,
                                                  const float* __restrict__ bn1s,
                                                  const float* __restrict__ bn1b) {
    __shared__ __align__(16) float  sin[2*16*15*C2P];   // [s][ci][y:15][x pitch22]
    __shared__ __align__(16) float2 swp[16*16*10];      // [ci][cp][10]
    __shared__ float sg1[64], sb1[64];
    __shared__ float ssum[32], sssq[32];
    int n0 = blockIdx.x * 2, tid = threadIdx.x;
    int s = tid / 288, r = tid % 288, pg = r % 36, cog = r / 36;   // cog 0..7
    int y0 = (pg / 6) * 2, x0 = (pg % 6) * 2;

    if (tid < 64) {
        float m  = g_sum1[tid] * (1.f / 460800.f);
        float vv = fmaxf(g_ssq1[tid] * (1.f / 460800.f) - m*m, 0.f);
        float gg = bn1s[tid] * rsqrtf(vv + BN_EPS);
        sg1[tid] = gg; sb1[tid] = bn1b[tid] - m * gg;
    }
    if (tid < 32) { ssum[tid] = 0.f; sssq[tid] = 0.f; }

    // column-staging identity (computed once)
    int st_ss = tid / 240, st_rem = tid % 240, st_ci = st_rem / 15, st_xx = st_rem % 15;

    u64 acc[2][4];                                      // [pair j][pos]
#pragma unroll
    for (int j = 0; j < 2; j++)
#pragma unroll
        for (int p = 0; p < 4; p++) acc[j][p] = 0ull;

    for (int ch = 0; ch < 4; ch++) {
        __syncthreads();
        // column staging: thread = (ss, ci, xx), loops y (BN1 applied)
        if (tid < 480) {
            int c = ch*16 + st_ci;
            const float* src = g_a1 + (size_t)(n0+st_ss)*A1_PER + c*225 + st_xx;
            float* dst = sin + (st_ss*16 + st_ci)*330 + st_xx;
            float gg = sg1[c], bb = sb1[c];
#pragma unroll
            for (int y = 0; y < 15; y++)
                dst[y*C2P] = fmaf(src[y*15], gg, bb);
        }
        {
            const float4* wsrc = (const float4*)(g_w2p + (size_t)ch*2560);
            float4* wdst = (float4*)swp;
            for (int i = tid; i < 1280; i += 576) wdst[i] = wsrc[i];
        }
        __syncthreads();

        const float* sp = sin + s*16*330 + y0*C2P + x0;
#pragma unroll 2
        for (int ci = 0; ci < 16; ci++) {
            u64 pp[4][4];
#pragma unroll
            for (int rr = 0; rr < 4; rr++) {
                float2 f01 = *(const float2*)(sp + ci*330 + rr*C2P);
                float2 f23 = *(const float2*)(sp + ci*330 + rr*C2P + 2);
                pp[rr][0] = dup2(f01.x); pp[rr][1] = dup2(f01.y);
                pp[rr][2] = dup2(f23.x); pp[rr][3] = dup2(f23.y);
            }
            const ulonglong2* wv = (const ulonglong2*)(swp + (ci*16 + cog*2)*10);
#pragma unroll
            for (int j = 0; j < 2; j++) {
                ulonglong2 wa = wv[j*5+0], wb = wv[j*5+1], wc = wv[j*5+2],
                           wd = wv[j*5+3], we = wv[j*5+4];
                u64 wk[9] = {wa.x, wa.y, wb.x, wb.y, wc.x, wc.y, wd.x, wd.y, we.x};
#pragma unroll
                for (int ky = 0; ky < 3; ky++)
#pragma unroll
                    for (int kx = 0; kx < 3; kx++) {
                        u64 w = wk[ky*3+kx];
                        acc[j][0] = fma2(w, pp[ky  ][kx  ], acc[j][0]);
                        acc[j][1] = fma2(w, pp[ky  ][kx+1], acc[j][1]);
                        acc[j][2] = fma2(w, pp[ky+1][kx  ], acc[j][2]);
                        acc[j][3] = fma2(w, pp[ky+1][kx+1], acc[j][3]);
                    }
            }
        }
    }

#pragma unroll
    for (int j = 0; j < 2; j++) {
        float2 a0 = unpack2(acc[j][0]), a1v = unpack2(acc[j][1]);
        float2 a2v = unpack2(acc[j][2]), a3 = unpack2(acc[j][3]);
        int co = cog*4 + 2*j;
        float va = fmaxf(fmaxf(a0.x, a1v.x), fmaxf(a2v.x, a3.x)) + __ldg(c2b + co);
        float vb = fmaxf(fmaxf(a0.y, a1v.y), fmaxf(a2v.y, a3.y)) + __ldg(c2b + co + 1);
        va = fmaxf(va, 0.f); vb = fmaxf(vb, 0.f);
        *(float2*)(g_a2 + ((size_t)(n0+s)*36 + pg)*32 + co) = make_float2(va, vb);
        atomicAdd(&ssum[co],   va); atomicAdd(&sssq[co],   va*va);
        atomicAdd(&ssum[co+1], vb); atomicAdd(&sssq[co+1], vb*vb);
    }
    __syncthreads();
    if (tid < 32) {
        atomicAdd(g_sum2 + tid, ssum[tid]);
        atomicAdd(g_ssq2 + tid, sssq[tid]);
    }
}

// ---------------- conv3 (proven, fused BN2 coef) ----------------
#define C3_SW   0
#define C3_SIN  12288
#define C3_ST   17040
#define C3_CF   17104
#define CONV3_SMEM (17168 * 4)
__global__ void __launch_bounds__(256) k_conv3(const float* __restrict__ bias,
                                               const float* __restrict__ bn2s,
                                               const float* __restrict__ bn2b) {
    extern __shared__ __align__(16) float sm3[];
    float* sw3  = sm3 + C3_SW;
    float* sin2 = sm3 + C3_SIN;
    float* ssum = sm3 + C3_ST;
    float* sssq = sm3 + C3_ST + 32;
    float* sg2  = sm3 + C3_CF;
    float* sb2c = sm3 + C3_CF + 32;
    int n0 = blockIdx.x * 4, tid = threadIdx.x;

    if (tid < 32) {
        float m  = g_sum2[tid] * (1.f / 73728.f);
        float vv = fmaxf(g_ssq2[tid] * (1.f / 73728.f) - m*m, 0.f);
        float gg = bn2s[tid] * rsqrtf(vv + BN_EPS);
        sg2[tid] = gg; sb2c[tid] = bn2b[tid] - m * gg;
        ssum[tid] = 0.f; sssq[tid] = 0.f;
    }
    __syncthreads();

    {
        const float4* wsrc = (const float4*)g_w3p;
        float4* wdst = (float4*)sw3;
        for (int i = tid; i < 3072; i += 256) wdst[i] = wsrc[i];
    }
    for (int i = tid; i < 4608; i += 256) {
        int s = i / 1152, j = i % 1152, pos = j / 32, c = j & 31;
        sin2[s*1188 + pos*33 + c] = fmaf(g_a2[(size_t)(n0+s)*A2_PER + j], sg2[c], sb2c[c]);
    }
    __syncthreads();

    int s = tid / 64, r = tid % 64, pos = r % 16, grp = r / 16;
    int py = pos / 4, px = pos % 4;
    float acc[8];
#pragma unroll
    for (int a = 0; a < 8; a++) acc[a] = 0.f;

    const float* sb2 = sin2 + s*1188;
    for (int ci = 0; ci < 32; ci++) {
        float p[9];
#pragma unroll
        for (int ky = 0; ky < 3; ky++)
#pragma unroll
            for (int kx = 0; kx < 3; kx++) p[ky*3+kx] = sb2[((py+ky)*6 + px+kx)*33 + ci];
        const float* wb = sw3 + (ci*32 + grp*8)*12;
#pragma unroll
        for (int cl = 0; cl < 8; cl++) {
            const float4* w4 = (const float4*)(wb + cl*12);
            float4 wa = w4[0], wc = w4[1];
            float wv[9] = {wa.x, wa.y, wa.z, wa.w, wc.x, wc.y, wc.z, wc.w, wb[cl*12+8]};
            float a = acc[cl];
#pragma unroll
            for (int k = 0; k < 9; k++) a = fmaf(wv[k], p[k], a);
            acc[cl] = a;
        }
    }
#pragma unroll
    for (int cl = 0; cl < 8; cl++) {
        int co = grp*8 + cl;
        float v = fmaxf(acc[cl] + bias[co], 0.f);
        g_hp[(size_t)(n0+s)*H_PER + co*16 + pos] = v;
        atomicAdd(&ssum[co], v);
        atomicAdd(&sssq[co], v*v);
    }
    __syncthreads();
    if (tid < 32) {
        atomicAdd(g_sum3 + tid, ssum[tid]);
        atomicAdd(g_ssq3 + tid, sssq[tid]);
    }
}

// ---------------- vqfc v3: 2 samples/block, 256 threads ----------------
__global__ void __launch_bounds__(256) k_vqfc(const float* __restrict__ cb,
                                              const float* __restrict__ fc1w,
                                              const float* __restrict__ fc1b,
                                              const float* __restrict__ fc2w,
                                              const float* __restrict__ fc2b,
                                              const float* __restrict__ bn3s,
                                              const float* __restrict__ bn3b,
                                              float* __restrict__ out) {
    __shared__ float scb[KCB*32];        // row-major (recon gather)
    __shared__ float scbT[32*104];       // transposed, pad 104
    __shared__ float scbsq[104];
    __shared__ float hs[1024];           // [s][512]
    __shared__ float bl[1024];
    __shared__ float z1[128];            // [s][64]
    __shared__ float z1h[256];
    __shared__ int   idxs[32];           // [s][16]
    __shared__ float wred[8];
    __shared__ float sg3[32], sb3c[32];
    int n0 = blockIdx.x * 2, tid = threadIdx.x;
    unsigned full = 0xffffffffu;

    if (tid < 32) {
        float m  = g_sum3[tid] * (1.f / 32768.f);
        float vv = fmaxf(g_ssq3[tid] * (1.f / 32768.f) - m*m, 0.f);
        float gg = bn3s[tid] * rsqrtf(vv + BN_EPS);
        sg3[tid] = gg; sb3c[tid] = bn3b[tid] - m * gg;
    }
    __syncthreads();

    for (int i = tid; i < KCB*32; i += 256) {
        float v = cb[i];
        scb[i] = v;
        scbT[(i & 31)*104 + (i >> 5)] = v;
    }
    if (tid < KCB) scbsq[tid] = g_cbsq[tid];
    for (int i = tid; i < 1024; i += 256) {
        int s = i >> 9, j = i & 511, c = j >> 4;
        float v = fmaf(g_hp[(size_t)(n0+s)*H_PER + j], sg3[c], sb3c[c]);
        hs[i] = v;
        out[H_OFF + (size_t)(n0+s)*512 + j] = v;
    }
    __syncthreads();

    // VQ argmin: thread = (s, pos, sub)
    {
        int s = tid >> 7, r = tid & 127, pos = r >> 3, sub = r & 7;
        float z[32];
#pragma unroll
        for (int c = 0; c < 32; c++) z[c] = hs[s*512 + c*16 + pos];
        float zz = 0.f;
#pragma unroll
        for (int c = 0; c < 32; c++) zz = fmaf(z[c], z[c], zz);
        float bd = INFINITY; int bi = 0;
        for (int k = sub; k < KCB; k += 8) {
            float dot = 0.f;
#pragma unroll
            for (int c = 0; c < 32; c++) dot = fmaf(scbT[c*104 + k], z[c], dot);
            float d = zz + scbsq[k] - 2.f*dot;
            if (d < bd) { bd = d; bi = k; }
        }
#pragma unroll
        for (int off = 4; off; off >>= 1) {
            float od = __shfl_down_sync(full, bd, off, 8);
            int   oi = __shfl_down_sync(full, bi, off, 8);
            if (od < bd || (od == bd && oi < bi)) { bd = od; bi = oi; }
        }
        if (sub == 0) idxs[s*16 + pos] = bi;
    }
    __syncthreads();

    // recon / blend / vq partial over both samples
    float vqs = 0.f;
    for (int i = tid; i < 1024; i += 256) {
        int s = i >> 9, j = i & 511, c = j >> 4, p2 = j & 15;
        float q = scb[idxs[s*16 + p2]*32 + c];
        float zv = hs[i];
        float df = q - zv;
        vqs = fmaf(df, df, vqs);
        out[RECON_OFF + (size_t)(n0+s)*512 + j] = q;
        bl[i] = fmaf(0.5f, q, zv);
    }
    vqs = wredsum(vqs);
    if ((tid & 31) == 0) wred[tid >> 5] = vqs;
    __syncthreads();
    if (tid == 0) {
        float a = 0.f;
#pragma unroll
        for (int w = 0; w < 8; w++) a += wred[w];
        atomicAdd(&g_vq, a);
    }

    // FC1: thread = (ss, hh, o); float4 LDG x float4 smem
    {
        int o = tid & 63, hh = (tid >> 6) & 1, ss = tid >> 7;
        const float4* wp4 = (const float4*)(fc1w + o*512 + hh*256);
        const float4* bl4 = (const float4*)(bl + ss*512 + hh*256);
        float a = 0.f;
#pragma unroll 8
        for (int t = 0; t < 64; t++) {
            float4 w = wp4[t], b = bl4[t];
            a = fmaf(w.x, b.x, a); a = fmaf(w.y, b.y, a);
            a = fmaf(w.z, b.z, a); a = fmaf(w.w, b.w, a);
        }
        z1h[tid] = a;     // layout: ss*128 + hh*64 + o
    }
    __syncthreads();
    if (tid < 128) {
        int ss = tid >> 6, o = tid & 63;
        z1[ss*64 + o] = fmaxf(z1h[ss*128 + o] + z1h[ss*128 + 64 + o] + fc1b[o], 0.f);
    }
    __syncthreads();

    // FC2 + log_softmax: warp 0 -> sample 0, warp 1 -> sample 1
    if (tid < 64) {
        int s = tid >> 5, lane = tid & 31;
        float y = -INFINITY;
        if (lane < 10) {
            const float* wp = fc2w + lane*64;
            float a = 0.f;
#pragma unroll
            for (int j = 0; j < 64; j++) a = fmaf(wp[j], z1[s*64 + j], a);
            y = a + fc2b[lane];
        }
        float m = y;
#pragma unroll
        for (int off = 16; off; off >>= 1) m = fmaxf(m, __shfl_xor_sync(full, m, off));
        float e = (lane < 10) ? expf(y - m) : 0.f;
        float ssum = e;
#pragma unroll
        for (int off = 16; off; off >>= 1) ssum += __shfl_xor_sync(full, ssum, off);
        if (lane < 10) out[LP_OFF + (size_t)(n0+s)*10 + lane] = y - m - logf(ssum);
    }
}

__global__ void k_final(float* __restrict__ out) {
    out[LOSS_OFF] = 1.25f * g_vq / (float)(B * 16 * 32);
}

// ---------------- launch ----------------
extern "C" void kernel_launch(void* const* d_in, const int* in_sizes, int n_in,
                              void* d_out, int out_size) {
    const float* x      = (const float*)d_in[0];
    const float* c1w    = (const float*)d_in[1];
    const float* c1b    = (const float*)d_in[2];
    const float* bn1s   = (const float*)d_in[3];
    const float* bn1b   = (const float*)d_in[4];
    const float* c2w    = (const float*)d_in[5];
    const float* c2b    = (const float*)d_in[6];
    const float* bn2s   = (const float*)d_in[7];
    const float* bn2b   = (const float*)d_in[8];
    const float* c3w    = (const float*)d_in[9];
    const float* c3b    = (const float*)d_in[10];
    const float* bn3s   = (const float*)d_in[11];
    const float* bn3b   = (const float*)d_in[12];
    const float* cb     = (const float*)d_in[13];
    const float* fc1w   = (const float*)d_in[14];
    const float* fc1b   = (const float*)d_in[15];
    const float* fc2w   = (const float*)d_in[16];
    const float* fc2b   = (const float*)d_in[17];
    float* out = (float*)d_out;

    cudaFuncSetAttribute(k_conv3, cudaFuncAttributeMaxDynamicSharedMemorySize, CONV3_SMEM);

    k_setup<<<48, 256>>>(cb, c1w, c2w, c3w);                       // 0
    k_conv1<<<B, 256>>>(x, c1b);                                   // 1
    k_stats0<<<B, 256>>>();                                        // 2
    k_conv2<<<B/2, 576>>>(c2b, bn1s, bn1b);                        // 3  <- ncu capture
    k_conv3<<<B/4, 256, CONV3_SMEM>>>(c3b, bn2s, bn2b);            // 4
    k_vqfc<<<B/2, 256>>>(cb, fc1w, fc1b, fc2w, fc2b, bn3s, bn3b, out); // 5
    k_final<<<1, 1>>>(out);                                        // 6
}